// round 12
// baseline (speedup 1.0000x reference)
#include <cuda_runtime.h>
#include <math.h>
#include <cstdint>

// Problem dims (fixed)
#define BDIM 2
#define TDIM 2048
#define CDIM 1024
#define NH   16
#define HD   64
#define MROWS (BDIM*TDIM)   // 4096

// ---------------- device scratch (no allocations allowed) ----------------
__device__ float g_q[(size_t)MROWS*CDIM];   // q after rope (natural layout)
__device__ float g_k[(size_t)MROWS*HD];     // k pre-rope (natural, gemm out)
__device__ float g_k2[(size_t)MROWS*HD];    // k post-rope, paired-transposed tiles
__device__ float g_v[(size_t)MROWS*HD];     // v paired tiles (gemm writes directly)
__device__ float g_att[(size_t)MROWS*CDIM]; // attn out, tf32-prerounded (natural)
__device__ float g_xr[(size_t)MROWS*CDIM];  // x  tf32-prerounded
__device__ float g_wqr[(size_t)CDIM*CDIM];  // Wq tf32-prerounded
__device__ float g_wor[(size_t)CDIM*CDIM];  // Wo tf32-prerounded

// ======================= helpers =========================================
__device__ __forceinline__ float to_tf32(float x) {
    float r; asm("cvt.rna.tf32.f32 %0, %1;" : "=f"(r) : "f"(x)); return r;
}
__device__ __forceinline__ void mma_tf32(float* c,
    uint32_t a0, uint32_t a1, uint32_t a2, uint32_t a3,
    uint32_t b0, uint32_t b1)
{
    asm volatile(
        "mma.sync.aligned.m16n8k8.row.col.f32.tf32.tf32.f32 "
        "{%0,%1,%2,%3}, {%4,%5,%6,%7}, {%8,%9}, {%0,%1,%2,%3};"
        : "+f"(c[0]), "+f"(c[1]), "+f"(c[2]), "+f"(c[3])
        : "r"(a0), "r"(a1), "r"(a2), "r"(a3), "r"(b0), "r"(b1));
}
__device__ __forceinline__ uint32_t smem_u32(const void* p) {
    uint32_t a;
    asm("{ .reg .u64 t; cvta.to.shared.u64 t, %1; cvt.u32.u64 %0, t; }"
        : "=r"(a) : "l"(p));
    return a;
}
#define CP_ASYNC16(dst_u32, src_ptr) \
    asm volatile("cp.async.cg.shared.global [%0], [%1], 16;" \
        :: "r"(dst_u32), "l"(src_ptr) : "memory")
#define CP_COMMIT() asm volatile("cp.async.commit_group;" ::: "memory")
#define CP_WAIT0()  asm volatile("cp.async.wait_group 0;"  ::: "memory")
#define CP_WAIT1()  asm volatile("cp.async.wait_group 1;"  ::: "memory")

// =========================================================================
// tf32 round-copy (RNA): out[i] = tf32(in[i]); n multiple of 4.
// =========================================================================
__global__ void round4_kernel(const float4* __restrict__ in,
                              float4* __restrict__ out, int n4)
{
    int i = blockIdx.x * blockDim.x + threadIdx.x;
    if (i >= n4) return;
    float4 v = in[i];
    v.x = to_tf32(v.x); v.y = to_tf32(v.y); v.z = to_tf32(v.z); v.w = to_tf32(v.w);
    out[i] = v;
}

// =========================================================================
// 3-stage cp.async pipelined tf32 GEMM (inputs PRE-ROUNDED to tf32):
//   C[M,N] = A[M,K] @ B[K,N] + bias[N]
// BM=128, BN=128, BK=16, 256 threads = 8 warps (2m x 4n).   [measured 69.4us]
// =========================================================================
#define GP_AS  20
#define GP_BNS 136
#define GP_AST (128*GP_AS)          // 2560 floats
#define GP_BST (16*GP_BNS)          // 2176 floats
#define GP_STF (GP_AST+GP_BST)      // 4736 floats per stage
#define GP_SMEM (3*GP_STF*4)        // 56832 bytes

__global__ void __launch_bounds__(256)
tc_gemm_pipe_kernel(const float* __restrict__ A, const float* __restrict__ B,
                    const float* __restrict__ bias, float* __restrict__ C,
                    int M, int N, int K)
{
    constexpr int BK = 16;
    extern __shared__ float sm[];
    const uint32_t sbase = smem_u32(sm);

    const int tid   = threadIdx.x;
    const int lane  = tid & 31;
    const int w     = tid >> 5;
    const int warpM = w & 1;
    const int warpN = w >> 1;
    const int g     = lane >> 2;
    const int qd    = lane & 3;
    const int rowBase = blockIdx.y * 128;
    const int colBase = blockIdx.x * 128;

    // 4 cp.async 16B chunks per thread per stage (A: 512 chunks, B: 512)
    const float* gsrc[4]; uint32_t soff[4]; size_t jstr[4];
#pragma unroll
    for (int i = 0; i < 4; i++) {
        int idx = tid + i * 256;
        if (idx < 512) {
            int r = idx >> 2, c4 = (idx & 3) * 4;
            gsrc[i] = A + (size_t)(rowBase + r) * K + c4;
            soff[i] = (uint32_t)(r * GP_AS + c4) * 4;
            jstr[i] = BK;
        } else {
            int e = idx - 512;
            int r = e >> 5, c4 = (e & 31) * 4;
            gsrc[i] = B + (size_t)r * N + colBase + c4;
            soff[i] = (uint32_t)(GP_AST + r * GP_BNS + c4) * 4;
            jstr[i] = (size_t)BK * N;
        }
    }
    auto issue = [&](int j, int s) {
        const uint32_t sb = sbase + (uint32_t)s * (GP_STF * 4);
#pragma unroll
        for (int i = 0; i < 4; i++)
            CP_ASYNC16(sb + soff[i], gsrc[i] + (size_t)j * jstr[i]);
        CP_COMMIT();
    };

    const int NI = K / BK;   // 64

    float acc[4][4][4];
#pragma unroll
    for (int mt = 0; mt < 4; mt++)
#pragma unroll
        for (int nt = 0; nt < 4; nt++)
#pragma unroll
            for (int i = 0; i < 4; i++) acc[mt][nt][i] = 0.0f;

    issue(0, 0);
    issue(1, 1);

    int s = 0;
    for (int j = 0; j < NI; j++) {
        CP_WAIT1();
        __syncthreads();

        if (j + 2 < NI) {
            int s2 = s + 2; if (s2 >= 3) s2 -= 3;
            issue(j + 2, s2);
        } else {
            CP_COMMIT();   // empty group keeps wait_group accounting aligned
        }

        const float* Ab = sm + s * GP_STF;
        const float* Bb = Ab + GP_AST;
#pragma unroll
        for (int kk = 0; kk < BK; kk += 8) {
            uint32_t afr[4][4];
#pragma unroll
            for (int mt = 0; mt < 4; mt++) {
                const int m0 = warpM * 64 + mt * 16;
                afr[mt][0] = __float_as_uint(Ab[(m0 + g    ) * GP_AS + kk + qd    ]);
                afr[mt][1] = __float_as_uint(Ab[(m0 + g + 8) * GP_AS + kk + qd    ]);
                afr[mt][2] = __float_as_uint(Ab[(m0 + g    ) * GP_AS + kk + qd + 4]);
                afr[mt][3] = __float_as_uint(Ab[(m0 + g + 8) * GP_AS + kk + qd + 4]);
            }
            uint32_t bfr[4][2];
#pragma unroll
            for (int nt = 0; nt < 4; nt++) {
                const int n0 = warpN * 32 + nt * 8;
                bfr[nt][0] = __float_as_uint(Bb[(kk + qd    ) * GP_BNS + n0 + g]);
                bfr[nt][1] = __float_as_uint(Bb[(kk + qd + 4) * GP_BNS + n0 + g]);
            }
#pragma unroll
            for (int mt = 0; mt < 4; mt++)
#pragma unroll
                for (int nt = 0; nt < 4; nt++)
                    mma_tf32(acc[mt][nt], afr[mt][0], afr[mt][1], afr[mt][2], afr[mt][3],
                             bfr[nt][0], bfr[nt][1]);
        }
        if (++s == 3) s = 0;
    }

#pragma unroll
    for (int mt = 0; mt < 4; mt++) {
        const int row0 = rowBase + warpM * 64 + mt * 16 + g;
#pragma unroll
        for (int nt = 0; nt < 4; nt++) {
            const int c = colBase + warpN * 32 + nt * 8 + qd * 2;
            const float b0 = bias[c], b1 = bias[c + 1];
            float2 v0 = make_float2(acc[mt][nt][0] + b0, acc[mt][nt][1] + b1);
            float2 v1 = make_float2(acc[mt][nt][2] + b0, acc[mt][nt][3] + b1);
            *(float2*)&C[(size_t)row0 * N + c] = v0;
            *(float2*)&C[(size_t)(row0 + 8) * N + c] = v1;
        }
    }
}

// =========================================================================
// K and V projections fused: z=0 -> K natural, z=1 -> V paired tiles.
// =========================================================================
__global__ void __launch_bounds__(256)
tc_gemm_kv_kernel(const float* __restrict__ A,
                  const float* __restrict__ B0, const float* __restrict__ bias0,
                  float* __restrict__ C0,
                  const float* __restrict__ B1, const float* __restrict__ bias1,
                  float* __restrict__ C1,
                  int M, int N, int K)
{
    constexpr int BN  = 64;
    constexpr int BM  = 128;
    constexpr int BK  = 16;
    constexpr int AS  = BK + 4;
    constexpr int BNS = BN + 8;
    constexpr int A_FLOATS = BM * AS;
    constexpr int B_FLOATS = BK * BNS;
    constexpr int A_F4 = BM * BK / (4 * 256);
    constexpr int B_F4 = BK * BN / (4 * 256);
    constexpr int NT   = BN / 32;
    constexpr int WN   = BN / 4;

    const float* B    = blockIdx.z ? B1 : B0;
    const float* bias = blockIdx.z ? bias1 : bias0;
    float*       C    = blockIdx.z ? C1 : C0;

    extern __shared__ float sm[];
    float* As = sm;
    float* Bs = sm + 2 * A_FLOATS;

    const int tid   = threadIdx.x;
    const int lane  = tid & 31;
    const int w     = tid >> 5;
    const int warpM = w & 1;
    const int warpN = w >> 1;
    const int g     = lane >> 2;
    const int qd    = lane & 3;
    const int rowBase = blockIdx.y * BM;

    int ar[A_F4]; int akq[A_F4];
#pragma unroll
    for (int t = 0; t < A_F4; t++) {
        int idx = tid + t * 256;
        ar[t] = idx >> 2; akq[t] = (idx & 3) * 4;
    }
    int br[B_F4]; int bc4[B_F4];
#pragma unroll
    for (int t = 0; t < B_F4; t++) {
        int idx = tid + t * 256;
        br[t] = idx / (BN / 4); bc4[t] = (idx % (BN / 4)) * 4;
    }

    const int NI = K / BK;

    float acc[4][NT][4];
#pragma unroll
    for (int mt = 0; mt < 4; mt++)
#pragma unroll
        for (int nt = 0; nt < NT; nt++)
#pragma unroll
            for (int i = 0; i < 4; i++) acc[mt][nt][i] = 0.0f;

    float4 aR[A_F4], bR[B_F4];

    auto fetch = [&](int j) {
#pragma unroll
        for (int t = 0; t < A_F4; t++)
            aR[t] = *(const float4*)&A[(size_t)(rowBase + ar[t]) * K + j * BK + akq[t]];
#pragma unroll
        for (int t = 0; t < B_F4; t++)
            bR[t] = *(const float4*)&B[(size_t)(j * BK + br[t]) * N + bc4[t]];
    };
    auto stage = [&](int buf) {
        float* Ab = As + buf * A_FLOATS;
        float* Bb = Bs + buf * B_FLOATS;
#pragma unroll
        for (int t = 0; t < A_F4; t++) {
            float4 v = aR[t];
            v.x = to_tf32(v.x); v.y = to_tf32(v.y); v.z = to_tf32(v.z); v.w = to_tf32(v.w);
            *(float4*)&Ab[ar[t] * AS + akq[t]] = v;
        }
#pragma unroll
        for (int t = 0; t < B_F4; t++) {
            float4 v = bR[t];
            v.x = to_tf32(v.x); v.y = to_tf32(v.y); v.z = to_tf32(v.z); v.w = to_tf32(v.w);
            *(float4*)&Bb[br[t] * BNS + bc4[t]] = v;
        }
    };

    fetch(0); stage(0);
    __syncthreads();

    for (int j = 0; j < NI; j++) {
        const int buf = j & 1;
        if (j + 1 < NI) fetch(j + 1);

        const float* Ab = As + buf * A_FLOATS;
        const float* Bb = Bs + buf * B_FLOATS;
#pragma unroll
        for (int kk = 0; kk < BK; kk += 8) {
            uint32_t afr[4][4];
#pragma unroll
            for (int mt = 0; mt < 4; mt++) {
                const int m0 = warpM * 64 + mt * 16;
                afr[mt][0] = __float_as_uint(Ab[(m0 + g    ) * AS + kk + qd    ]);
                afr[mt][1] = __float_as_uint(Ab[(m0 + g + 8) * AS + kk + qd    ]);
                afr[mt][2] = __float_as_uint(Ab[(m0 + g    ) * AS + kk + qd + 4]);
                afr[mt][3] = __float_as_uint(Ab[(m0 + g + 8) * AS + kk + qd + 4]);
            }
            uint32_t bfr[NT][2];
#pragma unroll
            for (int nt = 0; nt < NT; nt++) {
                const int n0 = warpN * WN + nt * 8;
                bfr[nt][0] = __float_as_uint(Bb[(kk + qd    ) * BNS + n0 + g]);
                bfr[nt][1] = __float_as_uint(Bb[(kk + qd + 4) * BNS + n0 + g]);
            }
#pragma unroll
            for (int mt = 0; mt < 4; mt++)
#pragma unroll
                for (int nt = 0; nt < NT; nt++)
                    mma_tf32(acc[mt][nt], afr[mt][0], afr[mt][1], afr[mt][2], afr[mt][3],
                             bfr[nt][0], bfr[nt][1]);
        }

        if (j + 1 < NI) {
            stage(buf ^ 1);
            __syncthreads();
        }
    }

    if (blockIdx.z == 0) {
#pragma unroll
        for (int mt = 0; mt < 4; mt++) {
            const int row0 = rowBase + warpM * 64 + mt * 16 + g;
#pragma unroll
            for (int nt = 0; nt < NT; nt++) {
                const int c = warpN * WN + nt * 8 + qd * 2;
                const float b0 = bias[c], b1 = bias[c + 1];
                float2 v0 = make_float2(acc[mt][nt][0] + b0, acc[mt][nt][1] + b1);
                float2 v1 = make_float2(acc[mt][nt][2] + b0, acc[mt][nt][3] + b1);
                *(float2*)&C[(size_t)row0 * N + c] = v0;
                *(float2*)&C[(size_t)(row0 + 8) * N + c] = v1;
            }
        }
    } else {
        auto wv = [&](int r, int n, float val) {
            int gt = r >> 6, rlo = r & 63;
            int p = ((rlo >> 3) << 2) | (rlo & 3);
            int comp = (rlo >> 2) & 1;
            C[(((size_t)gt * 32 + p) * 64 + n) * 2 + comp] = to_tf32(val);
        };
#pragma unroll
        for (int mt = 0; mt < 4; mt++) {
            const int row0 = rowBase + warpM * 64 + mt * 16 + g;
#pragma unroll
            for (int nt = 0; nt < NT; nt++) {
                const int c = warpN * WN + nt * 8 + qd * 2;
                const float b0 = bias[c], b1 = bias[c + 1];
                wv(row0,     c,     acc[mt][nt][0] + b0);
                wv(row0,     c + 1, acc[mt][nt][1] + b1);
                wv(row0 + 8, c,     acc[mt][nt][2] + b0);
                wv(row0 + 8, c + 1, acc[mt][nt][3] + b1);
            }
        }
    }
}

// =========================================================================
// RoPE: q in-place (natural); k natural -> paired-transposed tiles (tf32).
// =========================================================================
__global__ void rope_kernel(float* __restrict__ q, const float* __restrict__ kin,
                            float* __restrict__ k2out)
{
    const int total = BDIM*TDIM*(NH+1)*(HD/2);
    int idx = blockIdx.x*blockDim.x + threadIdx.x;
    if (idx >= total) return;
    int pr   = idx & 31;
    int rest = idx >> 5;
    int hh   = rest % (NH+1);
    int bt   = rest / (NH+1);
    int t    = bt & (TDIM-1);

    float inv_freq = expf(-(float)pr * (9.2103403719761836f / 32.0f));
    float ang = (float)t * inv_freq;
    float sn, cs;
    sincosf(ang, &sn, &cs);

    if (hh < NH) {
        float* base = q + (size_t)bt*CDIM + hh*HD;
        float t1 = base[pr];
        float t2 = base[pr + 32];
        base[pr]      = t1*cs + t2*sn;
        base[pr + 32] = t1*sn - t2*cs;
    } else {
        const float* base = kin + (size_t)bt*HD;
        float t1 = base[pr];
        float t2 = base[pr + 32];
        float v1 = t1*cs + t2*sn;
        float v2 = t1*sn - t2*cs;
        int gt = bt >> 6, c = bt & 63;
        int d1 = pr, d2 = pr + 32;
        int p1 = ((d1 >> 3) << 2) | (d1 & 3), c1 = (d1 >> 2) & 1;
        int p2 = ((d2 >> 3) << 2) | (d2 & 3), c2 = (d2 >> 2) & 1;
        k2out[(((size_t)gt*32 + p1)*64 + c)*2 + c1] = to_tf32(v1);
        k2out[(((size_t)gt*32 + p2)*64 + c)*2 + c2] = to_tf32(v2);
    }
}

// =========================================================================
// Tensor-core causal MQA flash attention v4.  BQ=BKV=64, HD=64.
// 128 threads = 4 warps x 16 q-rows.
// 3-slot K/V ring (K_t -> slot 2t%3, V_t -> slot (2t+1)%3): K needed only
// during S, V only during PV, so 3 x 17KB slots + 17KB P/Q buffer = 69.6KB
// -> 3 CTAs/SM (12 warps) instead of 2 (8 warps).
// =========================================================================
#define KP2S 68
#define QPS  68
#define TILE_F2 (32*KP2S)                         // 2176 float2 = 17408 B
#define ATT_SMEM_BYTES (3*TILE_F2*8 + 64*QPS*4)   // 52224 + 17408 = 69632

__global__ void __launch_bounds__(128, 3)
attn_tc_kernel(const float* __restrict__ gq, const float2* __restrict__ gk2,
               const float2* __restrict__ gv2, float* __restrict__ go)
{
    extern __shared__ float sm[];
    float*  QP  = sm + 3*TILE_F2*2;               // after the 3 KV slots
    const uint32_t sbase = smem_u32(sm);

    const int qtile = (gridDim.x - 1) - blockIdx.x;   // heavy blocks first
    const int h     = blockIdx.y;
    const int b     = blockIdx.z;
    const int tid   = threadIdx.x;
    const int lane  = tid & 31;
    const int w     = tid >> 5;
    const int g     = lane >> 2;
    const int qd    = lane & 3;
    const int r0    = w * 16;
    const int qbase = qtile * 64;

    // one tile = 32 rows x 512B (gmem) -> 544B rows (smem); 8 chunks/thread
    auto issue_K = [&](int t, int slot) {
        const char* src = (const char*)(gk2 + (size_t)(b*32 + t) * 2048);
        const uint32_t db = sbase + (uint32_t)slot * (TILE_F2 * 8);
#pragma unroll
        for (int i = 0; i < 8; i++) {
            int idx = tid + i * 128;
            int row = idx >> 5, ch = (idx & 31) << 4;
            CP_ASYNC16(db + row * 544 + ch, src + row * 512 + ch);
        }
        CP_COMMIT();
    };
    auto issue_V = [&](int t, int slot) {
        const char* src = (const char*)(gv2 + (size_t)(b*32 + t) * 2048);
        const uint32_t db = sbase + (uint32_t)slot * (TILE_F2 * 8);
#pragma unroll
        for (int i = 0; i < 8; i++) {
            int idx = tid + i * 128;
            int row = idx >> 5, ch = (idx & 31) << 4;
            CP_ASYNC16(db + row * 544 + ch, src + row * 512 + ch);
        }
        CP_COMMIT();
    };

    issue_K(0, 0);     // group 0

    // ---- stage Q (scaled, tf32) into QP while K0 DMA runs ----
    {
        const float* qp = gq + ((size_t)(b*TDIM + qbase))*CDIM + h*HD;
#pragma unroll
        for (int i = 0; i < 8; i++) {
            int idx = tid + i*128;
            int r = idx >> 4, d4 = (idx & 15) << 2;
            float4 v = *(const float4*)(qp + (size_t)r*CDIM + d4);
            QP[r*QPS + d4+0] = to_tf32(v.x*0.125f);
            QP[r*QPS + d4+1] = to_tf32(v.y*0.125f);
            QP[r*QPS + d4+2] = to_tf32(v.z*0.125f);
            QP[r*QPS + d4+3] = to_tf32(v.w*0.125f);
        }
    }
    issue_V(0, 1);     // group 1
    __syncthreads();

    // ---- Q fragments in registers (persist across kv tiles) ----
    uint32_t aQ[8][4];
#pragma unroll
    for (int kk = 0; kk < 8; kk++) {
        const int kb = kk*8;
        aQ[kk][0] = __float_as_uint(QP[(r0+g  )*QPS + kb + qd    ]);
        aQ[kk][1] = __float_as_uint(QP[(r0+g+8)*QPS + kb + qd    ]);
        aQ[kk][2] = __float_as_uint(QP[(r0+g  )*QPS + kb + qd + 4]);
        aQ[kk][3] = __float_as_uint(QP[(r0+g+8)*QPS + kb + qd + 4]);
    }

    float m_[2] = {-1e30f, -1e30f};
    float l_[2] = {0.0f, 0.0f};
    float oacc[8][4];
#pragma unroll
    for (int nt = 0; nt < 8; nt++)
#pragma unroll
        for (int i = 0; i < 4; i++) oacc[nt][i] = 0.0f;

    int sK = 0, sV = 1;    // slot(K_t)=2t%3, slot(V_t)=(2t+1)%3
    for (int t = 0; t <= qtile; t++) {
        // ---- wait K_t (V_t may still be in flight), prefetch K_{t+1} ----
        CP_WAIT1();
        __syncthreads();
        {
            int sKn = sV + 1; if (sKn >= 3) sKn -= 3;   // slot for K_{t+1}
            if (t < qtile) issue_K(t + 1, sKn);
            else           CP_COMMIT();                  // keep group count aligned
        }

        const float2* KtP = (const float2*)sm + (size_t)sK * TILE_F2;

        // ---- S = Q K^T ----
        float sacc[8][4];
#pragma unroll
        for (int nt = 0; nt < 8; nt++)
#pragma unroll
            for (int i = 0; i < 4; i++) sacc[nt][i] = 0.0f;

#pragma unroll
        for (int kk = 0; kk < 8; kk++) {
            float2 bf[8];
#pragma unroll
            for (int nt = 0; nt < 8; nt++)
                bf[nt] = KtP[(kk*4+qd)*KP2S + nt*8 + g];
#pragma unroll
            for (int nt = 0; nt < 8; nt++)
                mma_tf32(sacc[nt], aQ[kk][0], aQ[kk][1], aQ[kk][2], aQ[kk][3],
                         __float_as_uint(bf[nt].x), __float_as_uint(bf[nt].y));
        }

        // ---- causal mask (diagonal tile only) ----
        if (t == qtile) {
            const int ra = r0 + g, rb = ra + 8;
#pragma unroll
            for (int nt = 0; nt < 8; nt++) {
                const int ca = nt*8 + qd*2;
                if (ca     > ra) sacc[nt][0] = -1e30f;
                if (ca + 1 > ra) sacc[nt][1] = -1e30f;
                if (ca     > rb) sacc[nt][2] = -1e30f;
                if (ca + 1 > rb) sacc[nt][3] = -1e30f;
            }
        }

        // ---- online softmax; P -> QP (tf32-rounded) ----
#pragma unroll
        for (int rr = 0; rr < 2; rr++) {
            float lm = -1e30f;
#pragma unroll
            for (int nt = 0; nt < 8; nt++)
                lm = fmaxf(lm, fmaxf(sacc[nt][2*rr], sacc[nt][2*rr+1]));
            lm = fmaxf(lm, __shfl_xor_sync(0xffffffffu, lm, 1));
            lm = fmaxf(lm, __shfl_xor_sync(0xffffffffu, lm, 2));
            float mnew  = fmaxf(m_[rr], lm);
            float alpha = __expf(m_[rr] - mnew);

            float ls = 0.0f;
#pragma unroll
            for (int nt = 0; nt < 8; nt++) {
                float p0 = __expf(sacc[nt][2*rr]   - mnew);
                float p1 = __expf(sacc[nt][2*rr+1] - mnew);
                ls += p0 + p1;
                *(float2*)&QP[(r0 + g + rr*8)*QPS + nt*8 + qd*2] =
                    make_float2(to_tf32(p0), to_tf32(p1));
            }
            ls += __shfl_xor_sync(0xffffffffu, ls, 1);
            ls += __shfl_xor_sync(0xffffffffu, ls, 2);

            m_[rr] = mnew;
            l_[rr] = l_[rr]*alpha + ls;
#pragma unroll
            for (int nt = 0; nt < 8; nt++) {
                oacc[nt][2*rr]   *= alpha;
                oacc[nt][2*rr+1] *= alpha;
            }
        }

        // ---- wait V_t (K_{t+1} in flight), prefetch V_{t+1} into K_t's slot ----
        CP_WAIT1();
        __syncthreads();      // also orders P writes before PV reads
        if (t < qtile) issue_V(t + 1, sK);
        else           CP_COMMIT();

        const float2* VsP = (const float2*)sm + (size_t)sV * TILE_F2;

        // ---- O += P V ----
#pragma unroll
        for (int kk = 0; kk < 8; kk++) {
            const int kb = kk*8;
            uint32_t pa0 = __float_as_uint(QP[(r0+g  )*QPS + kb + qd    ]);
            uint32_t pa1 = __float_as_uint(QP[(r0+g+8)*QPS + kb + qd    ]);
            uint32_t pa2 = __float_as_uint(QP[(r0+g  )*QPS + kb + qd + 4]);
            uint32_t pa3 = __float_as_uint(QP[(r0+g+8)*QPS + kb + qd + 4]);
            float2 bv[8];
#pragma unroll
            for (int nt = 0; nt < 8; nt++)
                bv[nt] = VsP[(kk*4+qd)*KP2S + nt*8 + g];
#pragma unroll
            for (int nt = 0; nt < 8; nt++)
                mma_tf32(oacc[nt], pa0, pa1, pa2, pa3,
                         __float_as_uint(bv[nt].x), __float_as_uint(bv[nt].y));
        }

        // advance ring: next K slot = sV+1, next V slot = old sK
        int sKn = sV + 1; if (sKn >= 3) sKn -= 3;
        int sVn = sK;
        sK = sKn; sV = sVn;
    }

    // ---- normalize + store (tf32-prerounded, natural layout) ----
#pragma unroll
    for (int rr = 0; rr < 2; rr++) {
        const float inv = 1.0f / l_[rr];
        float* op = go + ((size_t)(b*TDIM + qbase + r0 + g + rr*8))*CDIM + h*HD;
#pragma unroll
        for (int nt = 0; nt < 8; nt++) {
            *(float2*)&op[nt*8 + qd*2] =
                make_float2(to_tf32(oacc[nt][2*rr]*inv), to_tf32(oacc[nt][2*rr+1]*inv));
        }
    }
}

// =========================================================================
// launch
// =========================================================================
extern "C" void kernel_launch(void* const* d_in, const int* in_sizes, int n_in,
                              void* d_out, int out_size)
{
    const float* x  = (const float*)d_in[0];
    const float* Wq = (const float*)d_in[1];
    const float* bq = (const float*)d_in[2];
    const float* Wk = (const float*)d_in[3];
    const float* bk = (const float*)d_in[4];
    const float* Wv = (const float*)d_in[5];
    const float* bv = (const float*)d_in[6];
    const float* Wo = (const float*)d_in[7];
    const float* bo = (const float*)d_in[8];
    float* out = (float*)d_out;

    float *qp, *kp, *k2p, *vp, *ap, *xr, *wqr, *wor;
    cudaGetSymbolAddress((void**)&qp,  g_q);
    cudaGetSymbolAddress((void**)&kp,  g_k);
    cudaGetSymbolAddress((void**)&k2p, g_k2);
    cudaGetSymbolAddress((void**)&vp,  g_v);
    cudaGetSymbolAddress((void**)&ap,  g_att);
    cudaGetSymbolAddress((void**)&xr,  g_xr);
    cudaGetSymbolAddress((void**)&wqr, g_wqr);
    cudaGetSymbolAddress((void**)&wor, g_wor);

    constexpr int SM64 = (2*(128*20) + 2*(16*72)) * 4;   // 29696 B
    cudaFuncSetAttribute(tc_gemm_pipe_kernel,
        cudaFuncAttributeMaxDynamicSharedMemorySize, GP_SMEM);
    cudaFuncSetAttribute(tc_gemm_kv_kernel,
        cudaFuncAttributeMaxDynamicSharedMemorySize, SM64);
    cudaFuncSetAttribute(attn_tc_kernel,
        cudaFuncAttributeMaxDynamicSharedMemorySize, ATT_SMEM_BYTES);

    // tf32 pre-round x, Wq, Wo (RNA)
    {
        int n4x = MROWS*CDIM/4, n4w = CDIM*CDIM/4;
        round4_kernel<<<(n4x + 255)/256, 256>>>((const float4*)x,  (float4*)xr,  n4x);
        round4_kernel<<<(n4w + 255)/256, 256>>>((const float4*)Wq, (float4*)wqr, n4w);
        round4_kernel<<<(n4w + 255)/256, 256>>>((const float4*)Wo, (float4*)wor, n4w);
    }

    // Q = x @ Wq + bq   (pipelined, pre-rounded inputs)
    tc_gemm_pipe_kernel<<<dim3(CDIM/128, MROWS/128), 256, GP_SMEM>>>(
        xr, wqr, bq, qp, MROWS, CDIM, CDIM);
    // K (natural), V (paired) fused
    tc_gemm_kv_kernel<<<dim3(1, MROWS/128, 2), 256, SM64>>>(
        x, Wk, bk, kp, Wv, bv, vp, MROWS, HD, CDIM);

    // RoPE: q in-place, k natural -> paired
    {
        int total = BDIM*TDIM*(NH+1)*(HD/2);
        rope_kernel<<<(total + 255)/256, 256>>>(qp, kp, k2p);
    }

    // causal MQA attention (3-slot KV ring -> 3 CTAs/SM)
    attn_tc_kernel<<<dim3(TDIM/64, NH, BDIM), 128, ATT_SMEM_BYTES>>>(
        qp, (const float2*)k2p, (const float2*)vp, ap);

    // out = att @ Wo + bo  (pipelined; att pre-rounded by attention)
    tc_gemm_pipe_kernel<<<dim3(CDIM/128, MROWS/128), 256, GP_SMEM>>>(
        ap, wor, bo, out, MROWS, CDIM, CDIM);
}

// round 13
// speedup vs baseline: 1.1902x; 1.1902x over previous
#include <cuda_runtime.h>
#include <math.h>
#include <cstdint>

// Problem dims (fixed)
#define BDIM 2
#define TDIM 2048
#define CDIM 1024
#define NH   16
#define HD   64
#define MROWS (BDIM*TDIM)   // 4096

// ---------------- device scratch (no allocations allowed) ----------------
__device__ float g_q[(size_t)MROWS*CDIM];   // q after rope (natural layout)
__device__ float g_k[(size_t)MROWS*HD];     // k pre-rope (natural, gemm out)
__device__ float g_k2[(size_t)MROWS*HD];    // k post-rope, paired-transposed tiles
__device__ float g_v[(size_t)MROWS*HD];     // v paired tiles (gemm writes directly)
__device__ float g_att[(size_t)MROWS*CDIM]; // attn out, tf32-prerounded (natural)

// ======================= helpers =========================================
__device__ __forceinline__ float to_tf32(float x) {
    float r; asm("cvt.rna.tf32.f32 %0, %1;" : "=f"(r) : "f"(x)); return r;
}
__device__ __forceinline__ void mma_tf32(float* c,
    uint32_t a0, uint32_t a1, uint32_t a2, uint32_t a3,
    uint32_t b0, uint32_t b1)
{
    asm volatile(
        "mma.sync.aligned.m16n8k8.row.col.f32.tf32.tf32.f32 "
        "{%0,%1,%2,%3}, {%4,%5,%6,%7}, {%8,%9}, {%0,%1,%2,%3};"
        : "+f"(c[0]), "+f"(c[1]), "+f"(c[2]), "+f"(c[3])
        : "r"(a0), "r"(a1), "r"(a2), "r"(a3), "r"(b0), "r"(b1));
}
__device__ __forceinline__ uint32_t smem_u32(const void* p) {
    uint32_t a;
    asm("{ .reg .u64 t; cvta.to.shared.u64 t, %1; cvt.u32.u64 %0, t; }"
        : "=r"(a) : "l"(p));
    return a;
}
#define CP_ASYNC16(dst_u32, src_ptr) \
    asm volatile("cp.async.cg.shared.global [%0], [%1], 16;" \
        :: "r"(dst_u32), "l"(src_ptr) : "memory")
#define CP_COMMIT() asm volatile("cp.async.commit_group;" ::: "memory")
#define CP_WAIT0()  asm volatile("cp.async.wait_group 0;"  ::: "memory")
#define CP_WAIT1()  asm volatile("cp.async.wait_group 1;"  ::: "memory")

// =========================================================================
// 3-stage cp.async pipelined tf32 GEMM with tf32 cvt AT FRAGMENT LOAD
// (inputs are RAW fp32; rounding happens after LDS, before MMA — same
//  values as pre-rounding, no prep kernels needed).
//   C[M,N] = tf32(A[M,K]) @ tf32(B[K,N]) + bias[N]
// BM=128, BN=128, BK=16, 256 threads = 8 warps (2m x 4n).
// Fused KV tile: when gridDim.x==9, blockIdx.x==8 computes x@[Wk|Wv]:
//   cols 0..63  -> K natural into Ck (+bk)
//   cols 64..127-> V paired-scatter into Cv (+bv, tf32-rounded)
// =========================================================================
#define GP_AS  20
#define GP_BNS 136
#define GP_AST (128*GP_AS)          // 2560 floats
#define GP_BST (16*GP_BNS)          // 2176 floats
#define GP_STF (GP_AST+GP_BST)      // 4736 floats per stage
#define GP_SMEM (3*GP_STF*4)        // 56832 bytes

__global__ void __launch_bounds__(256)
tc_gemm_fused_kernel(const float* __restrict__ A,
                     const float* __restrict__ Bq, const float* __restrict__ biasq,
                     float* __restrict__ Cq,
                     const float* __restrict__ Wk, const float* __restrict__ bk,
                     float* __restrict__ Ck,
                     const float* __restrict__ Wv, const float* __restrict__ bv,
                     float* __restrict__ Cv)
{
    constexpr int BK = 16;
    constexpr int K  = CDIM;
    extern __shared__ float sm[];
    const uint32_t sbase = smem_u32(sm);

    const bool isKV = (blockIdx.x == 8);          // only when gridDim.x==9
    const int  Nq   = CDIM;

    const int tid   = threadIdx.x;
    const int lane  = tid & 31;
    const int w     = tid >> 5;
    const int warpM = w & 1;
    const int warpN = w >> 1;
    const int g     = lane >> 2;
    const int qd    = lane & 3;
    const int rowBase = blockIdx.y * 128;
    const int colBase = isKV ? 0 : blockIdx.x * 128;

    // 4 cp.async 16B chunks per thread per stage (A: 512 chunks, B: 512)
    const float* gsrc[4]; uint32_t soff[4]; size_t jstr[4];
#pragma unroll
    for (int i = 0; i < 4; i++) {
        int idx = tid + i * 256;
        if (idx < 512) {
            int r = idx >> 2, c4 = (idx & 3) * 4;
            gsrc[i] = A + (size_t)(rowBase + r) * K + c4;
            soff[i] = (uint32_t)(r * GP_AS + c4) * 4;
            jstr[i] = BK;
        } else {
            int e = idx - 512;
            int r = e >> 5, c4 = (e & 31) * 4;
            if (!isKV) {
                gsrc[i] = Bq + (size_t)r * Nq + colBase + c4;
                jstr[i] = (size_t)BK * Nq;
            } else {
                gsrc[i] = (c4 < 64) ? (Wk + (size_t)r * HD + c4)
                                    : (Wv + (size_t)r * HD + (c4 - 64));
                jstr[i] = (size_t)BK * HD;
            }
            soff[i] = (uint32_t)(GP_AST + r * GP_BNS + c4) * 4;
        }
    }
    auto issue = [&](int j, int s) {
        const uint32_t sb = sbase + (uint32_t)s * (GP_STF * 4);
#pragma unroll
        for (int i = 0; i < 4; i++)
            CP_ASYNC16(sb + soff[i], gsrc[i] + (size_t)j * jstr[i]);
        CP_COMMIT();
    };

    const int NI = K / BK;   // 64

    float acc[4][4][4];
#pragma unroll
    for (int mt = 0; mt < 4; mt++)
#pragma unroll
        for (int nt = 0; nt < 4; nt++)
#pragma unroll
            for (int i = 0; i < 4; i++) acc[mt][nt][i] = 0.0f;

    issue(0, 0);
    issue(1, 1);

    int s = 0;
    for (int j = 0; j < NI; j++) {
        CP_WAIT1();
        __syncthreads();

        if (j + 2 < NI) {
            int s2 = s + 2; if (s2 >= 3) s2 -= 3;
            issue(j + 2, s2);
        } else {
            CP_COMMIT();   // empty group keeps wait_group accounting aligned
        }

        const float* Ab = sm + s * GP_STF;
        const float* Bb = Ab + GP_AST;
#pragma unroll
        for (int kk = 0; kk < BK; kk += 8) {
            uint32_t afr[4][4];
#pragma unroll
            for (int mt = 0; mt < 4; mt++) {
                const int m0 = warpM * 64 + mt * 16;
                afr[mt][0] = __float_as_uint(to_tf32(Ab[(m0 + g    ) * GP_AS + kk + qd    ]));
                afr[mt][1] = __float_as_uint(to_tf32(Ab[(m0 + g + 8) * GP_AS + kk + qd    ]));
                afr[mt][2] = __float_as_uint(to_tf32(Ab[(m0 + g    ) * GP_AS + kk + qd + 4]));
                afr[mt][3] = __float_as_uint(to_tf32(Ab[(m0 + g + 8) * GP_AS + kk + qd + 4]));
            }
            uint32_t bfr[4][2];
#pragma unroll
            for (int nt = 0; nt < 4; nt++) {
                const int n0 = warpN * 32 + nt * 8;
                bfr[nt][0] = __float_as_uint(to_tf32(Bb[(kk + qd    ) * GP_BNS + n0 + g]));
                bfr[nt][1] = __float_as_uint(to_tf32(Bb[(kk + qd + 4) * GP_BNS + n0 + g]));
            }
#pragma unroll
            for (int mt = 0; mt < 4; mt++)
#pragma unroll
                for (int nt = 0; nt < 4; nt++)
                    mma_tf32(acc[mt][nt], afr[mt][0], afr[mt][1], afr[mt][2], afr[mt][3],
                             bfr[nt][0], bfr[nt][1]);
        }
        if (++s == 3) s = 0;
    }

    if (!isKV) {
#pragma unroll
        for (int mt = 0; mt < 4; mt++) {
            const int row0 = rowBase + warpM * 64 + mt * 16 + g;
#pragma unroll
            for (int nt = 0; nt < 4; nt++) {
                const int c = colBase + warpN * 32 + nt * 8 + qd * 2;
                const float b0 = biasq[c], b1 = biasq[c + 1];
                float2 v0 = make_float2(acc[mt][nt][0] + b0, acc[mt][nt][1] + b1);
                float2 v1 = make_float2(acc[mt][nt][2] + b0, acc[mt][nt][3] + b1);
                *(float2*)&Cq[(size_t)row0 * Nq + c] = v0;
                *(float2*)&Cq[(size_t)(row0 + 8) * Nq + c] = v1;
            }
        }
    } else {
        // V paired-scatter (identical to old KV epilogue)
        auto wv = [&](int r, int n, float val) {
            int gt = r >> 6, rlo = r & 63;
            int p = ((rlo >> 3) << 2) | (rlo & 3);
            int comp = (rlo >> 2) & 1;
            Cv[(((size_t)gt * 32 + p) * 64 + n) * 2 + comp] = to_tf32(val);
        };
#pragma unroll
        for (int mt = 0; mt < 4; mt++) {
            const int row0 = rowBase + warpM * 64 + mt * 16 + g;
#pragma unroll
            for (int nt = 0; nt < 4; nt++) {
                const int c = warpN * 32 + nt * 8 + qd * 2;
                if (c < 64) {
                    const float b0 = bk[c], b1 = bk[c + 1];
                    float2 v0 = make_float2(acc[mt][nt][0] + b0, acc[mt][nt][1] + b1);
                    float2 v1 = make_float2(acc[mt][nt][2] + b0, acc[mt][nt][3] + b1);
                    *(float2*)&Ck[(size_t)row0 * HD + c] = v0;
                    *(float2*)&Ck[(size_t)(row0 + 8) * HD + c] = v1;
                } else {
                    const int cv = c - 64;
                    const float b0 = bv[cv], b1 = bv[cv + 1];
                    wv(row0,     cv,     acc[mt][nt][0] + b0);
                    wv(row0,     cv + 1, acc[mt][nt][1] + b1);
                    wv(row0 + 8, cv,     acc[mt][nt][2] + b0);
                    wv(row0 + 8, cv + 1, acc[mt][nt][3] + b1);
                }
            }
        }
    }
}

// =========================================================================
// RoPE: q in-place (natural); k natural -> paired-transposed tiles (tf32).
// =========================================================================
__global__ void rope_kernel(float* __restrict__ q, const float* __restrict__ kin,
                            float* __restrict__ k2out)
{
    const int total = BDIM*TDIM*(NH+1)*(HD/2);
    int idx = blockIdx.x*blockDim.x + threadIdx.x;
    if (idx >= total) return;
    int pr   = idx & 31;
    int rest = idx >> 5;
    int hh   = rest % (NH+1);
    int bt   = rest / (NH+1);
    int t    = bt & (TDIM-1);

    float inv_freq = expf(-(float)pr * (9.2103403719761836f / 32.0f));
    float ang = (float)t * inv_freq;
    float sn, cs;
    sincosf(ang, &sn, &cs);

    if (hh < NH) {
        float* base = q + (size_t)bt*CDIM + hh*HD;
        float t1 = base[pr];
        float t2 = base[pr + 32];
        base[pr]      = t1*cs + t2*sn;
        base[pr + 32] = t1*sn - t2*cs;
    } else {
        const float* base = kin + (size_t)bt*HD;
        float t1 = base[pr];
        float t2 = base[pr + 32];
        float v1 = t1*cs + t2*sn;
        float v2 = t1*sn - t2*cs;
        int gt = bt >> 6, c = bt & 63;
        int d1 = pr, d2 = pr + 32;
        int p1 = ((d1 >> 3) << 2) | (d1 & 3), c1 = (d1 >> 2) & 1;
        int p2 = ((d2 >> 3) << 2) | (d2 & 3), c2 = (d2 >> 2) & 1;
        k2out[(((size_t)gt*32 + p1)*64 + c)*2 + c1] = to_tf32(v1);
        k2out[(((size_t)gt*32 + p2)*64 + c)*2 + c2] = to_tf32(v2);
    }
}

// =========================================================================
// Tensor-core causal MQA flash attention (R9 version — measured best).
// 128 threads = 4 warps x 16 q-rows. smem = 2 KV double-buffers ONLY
// (69.6KB -> 3 CTAs/SM). Q staged through buffer1 slot, P transposed
// C-frag -> A-frag via quad shuffles (no smem P).
// =========================================================================
#define KP2S 68                  // K/V smem row stride in float2
#define TILE_F2 (32*KP2S)        // 2176 float2 per tile
#define BUF_F2  (2*TILE_F2)      // K+V per buffer
#define ATT3_SMEM_BYTES (2*BUF_F2*8)    // 69632

__global__ void __launch_bounds__(128, 3)
attn_tc_kernel(const float* __restrict__ gq, const float2* __restrict__ gk2,
               const float2* __restrict__ gv2, float* __restrict__ go)
{
    extern __shared__ float sm[];
    const uint32_t sbase = smem_u32(sm);

    const int qtile = (gridDim.x - 1) - blockIdx.x;   // heavy blocks first
    const int h     = blockIdx.y;
    const int b     = blockIdx.z;
    const int tid   = threadIdx.x;
    const int lane  = tid & 31;
    const int w     = tid >> 5;
    const int g     = lane >> 2;
    const int qd    = lane & 3;
    const int r0    = w * 16;
    const int qbase = qtile * 64;
    const unsigned FULL = 0xffffffffu;

    auto issue_tile = [&](int t, int buf) {
        const char* kgb = (const char*)(gk2 + (size_t)(b*32 + t) * 2048);
        const char* vgb = (const char*)(gv2 + (size_t)(b*32 + t) * 2048);
        const uint32_t kb = sbase + buf * (BUF_F2 * 8);
        const uint32_t vb = kb + TILE_F2 * 8;
#pragma unroll
        for (int i = 0; i < 8; i++) {
            int idx = tid + i * 128;
            int row = idx >> 5, ch = (idx & 31) << 4;
            CP_ASYNC16(kb + row * 544 + ch, kgb + row * 512 + ch);
            CP_ASYNC16(vb + row * 544 + ch, vgb + row * 512 + ch);
        }
        CP_COMMIT();
    };

    issue_tile(0, 0);   // DMA tile 0 into buffer 0

    // ---- stage Q (scaled, tf32) into buffer1's K slot (not yet in use) ----
    float* QP = sm + BUF_F2 * 2;    // float offset 8704 = start of buffer 1
#pragma unroll
    for (int i = 0; i < 8; i++) {
        int idx = tid + i*128;
        int r = idx >> 4, d4 = (idx & 15) << 2;
        const float* qp = gq + ((size_t)(b*TDIM + qbase))*CDIM + h*HD;
        float4 v = *(const float4*)(qp + (size_t)r*CDIM + d4);
        QP[r*68 + d4+0] = to_tf32(v.x*0.125f);
        QP[r*68 + d4+1] = to_tf32(v.y*0.125f);
        QP[r*68 + d4+2] = to_tf32(v.z*0.125f);
        QP[r*68 + d4+3] = to_tf32(v.w*0.125f);
    }
    __syncthreads();

    uint32_t aQ[8][4];
#pragma unroll
    for (int kk = 0; kk < 8; kk++) {
        const int kb = kk*8;
        aQ[kk][0] = __float_as_uint(QP[(r0+g  )*68 + kb + qd    ]);
        aQ[kk][1] = __float_as_uint(QP[(r0+g+8)*68 + kb + qd    ]);
        aQ[kk][2] = __float_as_uint(QP[(r0+g  )*68 + kb + qd + 4]);
        aQ[kk][3] = __float_as_uint(QP[(r0+g+8)*68 + kb + qd + 4]);
    }
    __syncthreads();   // all Q frags read before buffer1 gets tile-1 DMA

    float m_[2] = {-1e30f, -1e30f};
    float l_[2] = {0.0f, 0.0f};
    float oacc[8][4];
#pragma unroll
    for (int nt = 0; nt < 8; nt++)
#pragma unroll
        for (int i = 0; i < 4; i++) oacc[nt][i] = 0.0f;

    const int s1 = (lane & ~3) | (qd >> 1);   // P-transpose source lanes
    const int s2 = s1 + 2;
    const bool odd = qd & 1;

    for (int t = 0; t <= qtile; t++) {
        const int buf = t & 1;

        CP_WAIT0();
        __syncthreads();

        if (t < qtile) issue_tile(t + 1, buf ^ 1);

        const float2* KtP = (const float2*)sm + (size_t)buf * BUF_F2;
        const float2* VsP = KtP + TILE_F2;

        // ---- S = Q K^T ----
        float sacc[8][4];
#pragma unroll
        for (int nt = 0; nt < 8; nt++)
#pragma unroll
            for (int i = 0; i < 4; i++) sacc[nt][i] = 0.0f;

#pragma unroll
        for (int kk = 0; kk < 8; kk++) {
            float2 bf[8];
#pragma unroll
            for (int nt = 0; nt < 8; nt++)
                bf[nt] = KtP[(kk*4+qd)*KP2S + nt*8 + g];
#pragma unroll
            for (int nt = 0; nt < 8; nt++)
                mma_tf32(sacc[nt], aQ[kk][0], aQ[kk][1], aQ[kk][2], aQ[kk][3],
                         __float_as_uint(bf[nt].x), __float_as_uint(bf[nt].y));
        }

        // ---- causal mask (diagonal tile only) ----
        if (t == qtile) {
            const int ra = r0 + g, rb = ra + 8;
#pragma unroll
            for (int nt = 0; nt < 8; nt++) {
                const int ca = nt*8 + qd*2;
                if (ca     > ra) sacc[nt][0] = -1e30f;
                if (ca + 1 > ra) sacc[nt][1] = -1e30f;
                if (ca     > rb) sacc[nt][2] = -1e30f;
                if (ca + 1 > rb) sacc[nt][3] = -1e30f;
            }
        }

        // ---- online softmax; P kept in registers (tf32-rounded) ----
        float pe[8][4];   // pe[nt][rr*2+p] = P[g+8rr][nt*8+qd*2+p]
#pragma unroll
        for (int rr = 0; rr < 2; rr++) {
            float lm = -1e30f;
#pragma unroll
            for (int nt = 0; nt < 8; nt++)
                lm = fmaxf(lm, fmaxf(sacc[nt][2*rr], sacc[nt][2*rr+1]));
            lm = fmaxf(lm, __shfl_xor_sync(FULL, lm, 1));
            lm = fmaxf(lm, __shfl_xor_sync(FULL, lm, 2));
            float mnew  = fmaxf(m_[rr], lm);
            float alpha = __expf(m_[rr] - mnew);

            float ls = 0.0f;
#pragma unroll
            for (int nt = 0; nt < 8; nt++) {
                float p0 = __expf(sacc[nt][2*rr]   - mnew);
                float p1 = __expf(sacc[nt][2*rr+1] - mnew);
                ls += p0 + p1;
                pe[nt][2*rr+0] = to_tf32(p0);
                pe[nt][2*rr+1] = to_tf32(p1);
            }
            ls += __shfl_xor_sync(FULL, ls, 1);
            ls += __shfl_xor_sync(FULL, ls, 2);

            m_[rr] = mnew;
            l_[rr] = l_[rr]*alpha + ls;
#pragma unroll
            for (int nt = 0; nt < 8; nt++) {
                oacc[nt][2*rr]   *= alpha;
                oacc[nt][2*rr+1] *= alpha;
            }
        }

        // ---- O += P V  (P A-frags built via quad shuffles) ----
#pragma unroll
        for (int kk = 0; kk < 8; kk++) {
            float x0 = __shfl_sync(FULL, pe[kk][0], s1);
            float x1 = __shfl_sync(FULL, pe[kk][1], s1);
            float x2 = __shfl_sync(FULL, pe[kk][2], s1);
            float x3 = __shfl_sync(FULL, pe[kk][3], s1);
            float y0 = __shfl_sync(FULL, pe[kk][0], s2);
            float y1 = __shfl_sync(FULL, pe[kk][1], s2);
            float y2 = __shfl_sync(FULL, pe[kk][2], s2);
            float y3 = __shfl_sync(FULL, pe[kk][3], s2);
            uint32_t pa0 = __float_as_uint(odd ? x1 : x0);
            uint32_t pa1 = __float_as_uint(odd ? x3 : x2);
            uint32_t pa2 = __float_as_uint(odd ? y1 : y0);
            uint32_t pa3 = __float_as_uint(odd ? y3 : y2);

            float2 bv[8];
#pragma unroll
            for (int nt = 0; nt < 8; nt++)
                bv[nt] = VsP[(kk*4+qd)*KP2S + nt*8 + g];
#pragma unroll
            for (int nt = 0; nt < 8; nt++)
                mma_tf32(oacc[nt], pa0, pa1, pa2, pa3,
                         __float_as_uint(bv[nt].x), __float_as_uint(bv[nt].y));
        }
    }

    // ---- normalize + store (tf32-prerounded for the Wo GEMM) ----
#pragma unroll
    for (int rr = 0; rr < 2; rr++) {
        const float inv = 1.0f / l_[rr];
        float* op = go + ((size_t)(b*TDIM + qbase + r0 + g + rr*8))*CDIM + h*HD;
#pragma unroll
        for (int nt = 0; nt < 8; nt++) {
            *(float2*)&op[nt*8 + qd*2] =
                make_float2(to_tf32(oacc[nt][2*rr]*inv), to_tf32(oacc[nt][2*rr+1]*inv));
        }
    }
}

// =========================================================================
// launch
// =========================================================================
extern "C" void kernel_launch(void* const* d_in, const int* in_sizes, int n_in,
                              void* d_out, int out_size)
{
    const float* x  = (const float*)d_in[0];
    const float* Wq = (const float*)d_in[1];
    const float* bq = (const float*)d_in[2];
    const float* Wk = (const float*)d_in[3];
    const float* bk = (const float*)d_in[4];
    const float* Wv = (const float*)d_in[5];
    const float* bv = (const float*)d_in[6];
    const float* Wo = (const float*)d_in[7];
    const float* bo = (const float*)d_in[8];
    float* out = (float*)d_out;

    float *qp, *kp, *k2p, *vp, *ap;
    cudaGetSymbolAddress((void**)&qp,  g_q);
    cudaGetSymbolAddress((void**)&kp,  g_k);
    cudaGetSymbolAddress((void**)&k2p, g_k2);
    cudaGetSymbolAddress((void**)&vp,  g_v);
    cudaGetSymbolAddress((void**)&ap,  g_att);

    cudaFuncSetAttribute(tc_gemm_fused_kernel,
        cudaFuncAttributeMaxDynamicSharedMemorySize, GP_SMEM);
    cudaFuncSetAttribute(attn_tc_kernel,
        cudaFuncAttributeMaxDynamicSharedMemorySize, ATT3_SMEM_BYTES);

    // Q = x@Wq+bq  AND  K/V = x@[Wk|Wv]+b  in ONE launch (tile x==8 -> KV)
    tc_gemm_fused_kernel<<<dim3(9, MROWS/128), 256, GP_SMEM>>>(
        x, Wq, bq, qp,  Wk, bk, kp,  Wv, bv, vp);

    // RoPE: q in-place, k natural -> paired
    {
        int total = BDIM*TDIM*(NH+1)*(HD/2);
        rope_kernel<<<(total + 255)/256, 256>>>(qp, kp, k2p);
    }

    // causal MQA attention (R9 version, measured best)
    attn_tc_kernel<<<dim3(TDIM/64, NH, BDIM), 128, ATT3_SMEM_BYTES>>>(
        qp, (const float2*)k2p, (const float2*)vp, ap);

    // out = att @ Wo + bo  (att pre-rounded; Wo rounded at frag load)
    tc_gemm_fused_kernel<<<dim3(8, MROWS/128), 256, GP_SMEM>>>(
        ap, Wo, bo, out,  Wk, bk, kp,  Wv, bv, vp);   // KV path unused (grid.x=8)
}

// round 14
// speedup vs baseline: 1.6275x; 1.3674x over previous
#include <cuda_runtime.h>
#include <cuda_fp16.h>
#include <math.h>
#include <cstdint>

// Problem dims (fixed)
#define BDIM 2
#define TDIM 2048
#define CDIM 1024
#define NH   16
#define HD   64
#define MROWS (BDIM*TDIM)   // 4096

// ---------------- device scratch (no allocations allowed) ----------------
__device__ float  g_q[(size_t)MROWS*CDIM];   // q after rope (natural layout)
__device__ float  g_k[(size_t)MROWS*HD];     // k pre-rope (natural, gemm out)
__device__ __half g_k2h[(size_t)MROWS*HD];   // k post-rope, half, adjacent-d pairs per tile
__device__ __half g_vh[(size_t)MROWS*HD];    // v half, adjacent-kv pairs per tile
__device__ float  g_att[(size_t)MROWS*CDIM]; // attn out, tf32-prerounded (natural)

// Half-pair tile layouts (per 64-row kv tile, gt = global_row>>6):
//   K2h[gt][d>>1][c][d&1] = half(K[c][d])     (32 pair-rows x 64 cols x 2 halves)
//   Vh [gt][r>>1][n][r&1] = half(V[r][n])
// One tile = 32 x 128 halves = 8192 B, rows 256B contiguous (cp.async friendly).

// ======================= helpers =========================================
__device__ __forceinline__ float to_tf32(float x) {
    float r; asm("cvt.rna.tf32.f32 %0, %1;" : "=f"(r) : "f"(x)); return r;
}
__device__ __forceinline__ void mma_tf32(float* c,
    uint32_t a0, uint32_t a1, uint32_t a2, uint32_t a3,
    uint32_t b0, uint32_t b1)
{
    asm volatile(
        "mma.sync.aligned.m16n8k8.row.col.f32.tf32.tf32.f32 "
        "{%0,%1,%2,%3}, {%4,%5,%6,%7}, {%8,%9}, {%0,%1,%2,%3};"
        : "+f"(c[0]), "+f"(c[1]), "+f"(c[2]), "+f"(c[3])
        : "r"(a0), "r"(a1), "r"(a2), "r"(a3), "r"(b0), "r"(b1));
}
__device__ __forceinline__ void mma_f16(float* c,
    uint32_t a0, uint32_t a1, uint32_t a2, uint32_t a3,
    uint32_t b0, uint32_t b1)
{
    asm volatile(
        "mma.sync.aligned.m16n8k16.row.col.f32.f16.f16.f32 "
        "{%0,%1,%2,%3}, {%4,%5,%6,%7}, {%8,%9}, {%0,%1,%2,%3};"
        : "+f"(c[0]), "+f"(c[1]), "+f"(c[2]), "+f"(c[3])
        : "r"(a0), "r"(a1), "r"(a2), "r"(a3), "r"(b0), "r"(b1));
}
__device__ __forceinline__ uint32_t h2u(__half2 h) {
    uint32_t u; *(__half2*)&u = h; return u;
}
__device__ __forceinline__ uint32_t smem_u32(const void* p) {
    uint32_t a;
    asm("{ .reg .u64 t; cvta.to.shared.u64 t, %1; cvt.u32.u64 %0, t; }"
        : "=r"(a) : "l"(p));
    return a;
}
#define CP_ASYNC16(dst_u32, src_ptr) \
    asm volatile("cp.async.cg.shared.global [%0], [%1], 16;" \
        :: "r"(dst_u32), "l"(src_ptr) : "memory")
#define CP_COMMIT() asm volatile("cp.async.commit_group;" ::: "memory")
#define CP_WAIT0()  asm volatile("cp.async.wait_group 0;"  ::: "memory")
#define CP_WAIT1()  asm volatile("cp.async.wait_group 1;"  ::: "memory")

// =========================================================================
// 3-stage cp.async pipelined tf32 GEMM, cvt at fragment load (R13, measured).
// Fused KV tile: gridDim.x==9 & blockIdx.x==8 -> x@[Wk|Wv]:
//   cols 0..63 -> K natural fp32; cols 64..127 -> V half paired-scatter.
// =========================================================================
#define GP_AS  20
#define GP_BNS 136
#define GP_AST (128*GP_AS)
#define GP_BST (16*GP_BNS)
#define GP_STF (GP_AST+GP_BST)
#define GP_SMEM (3*GP_STF*4)        // 56832 bytes

__global__ void __launch_bounds__(256)
tc_gemm_fused_kernel(const float* __restrict__ A,
                     const float* __restrict__ Bq, const float* __restrict__ biasq,
                     float* __restrict__ Cq,
                     const float* __restrict__ Wk, const float* __restrict__ bk,
                     float* __restrict__ Ck,
                     const float* __restrict__ Wv, const float* __restrict__ bv,
                     __half* __restrict__ Cv)
{
    constexpr int BK = 16;
    constexpr int K  = CDIM;
    extern __shared__ float sm[];
    const uint32_t sbase = smem_u32(sm);

    const bool isKV = (blockIdx.x == 8);
    const int  Nq   = CDIM;

    const int tid   = threadIdx.x;
    const int lane  = tid & 31;
    const int w     = tid >> 5;
    const int warpM = w & 1;
    const int warpN = w >> 1;
    const int g     = lane >> 2;
    const int qd    = lane & 3;
    const int rowBase = blockIdx.y * 128;
    const int colBase = isKV ? 0 : blockIdx.x * 128;

    const float* gsrc[4]; uint32_t soff[4]; size_t jstr[4];
#pragma unroll
    for (int i = 0; i < 4; i++) {
        int idx = tid + i * 256;
        if (idx < 512) {
            int r = idx >> 2, c4 = (idx & 3) * 4;
            gsrc[i] = A + (size_t)(rowBase + r) * K + c4;
            soff[i] = (uint32_t)(r * GP_AS + c4) * 4;
            jstr[i] = BK;
        } else {
            int e = idx - 512;
            int r = e >> 5, c4 = (e & 31) * 4;
            if (!isKV) {
                gsrc[i] = Bq + (size_t)r * Nq + colBase + c4;
                jstr[i] = (size_t)BK * Nq;
            } else {
                gsrc[i] = (c4 < 64) ? (Wk + (size_t)r * HD + c4)
                                    : (Wv + (size_t)r * HD + (c4 - 64));
                jstr[i] = (size_t)BK * HD;
            }
            soff[i] = (uint32_t)(GP_AST + r * GP_BNS + c4) * 4;
        }
    }
    auto issue = [&](int j, int s) {
        const uint32_t sb = sbase + (uint32_t)s * (GP_STF * 4);
#pragma unroll
        for (int i = 0; i < 4; i++)
            CP_ASYNC16(sb + soff[i], gsrc[i] + (size_t)j * jstr[i]);
        CP_COMMIT();
    };

    const int NI = K / BK;

    float acc[4][4][4];
#pragma unroll
    for (int mt = 0; mt < 4; mt++)
#pragma unroll
        for (int nt = 0; nt < 4; nt++)
#pragma unroll
            for (int i = 0; i < 4; i++) acc[mt][nt][i] = 0.0f;

    issue(0, 0);
    issue(1, 1);

    int s = 0;
    for (int j = 0; j < NI; j++) {
        CP_WAIT1();
        __syncthreads();

        if (j + 2 < NI) {
            int s2 = s + 2; if (s2 >= 3) s2 -= 3;
            issue(j + 2, s2);
        } else {
            CP_COMMIT();
        }

        const float* Ab = sm + s * GP_STF;
        const float* Bb = Ab + GP_AST;
#pragma unroll
        for (int kk = 0; kk < BK; kk += 8) {
            uint32_t afr[4][4];
#pragma unroll
            for (int mt = 0; mt < 4; mt++) {
                const int m0 = warpM * 64 + mt * 16;
                afr[mt][0] = __float_as_uint(to_tf32(Ab[(m0 + g    ) * GP_AS + kk + qd    ]));
                afr[mt][1] = __float_as_uint(to_tf32(Ab[(m0 + g + 8) * GP_AS + kk + qd    ]));
                afr[mt][2] = __float_as_uint(to_tf32(Ab[(m0 + g    ) * GP_AS + kk + qd + 4]));
                afr[mt][3] = __float_as_uint(to_tf32(Ab[(m0 + g + 8) * GP_AS + kk + qd + 4]));
            }
            uint32_t bfr[4][2];
#pragma unroll
            for (int nt = 0; nt < 4; nt++) {
                const int n0 = warpN * 32 + nt * 8;
                bfr[nt][0] = __float_as_uint(to_tf32(Bb[(kk + qd    ) * GP_BNS + n0 + g]));
                bfr[nt][1] = __float_as_uint(to_tf32(Bb[(kk + qd + 4) * GP_BNS + n0 + g]));
            }
#pragma unroll
            for (int mt = 0; mt < 4; mt++)
#pragma unroll
                for (int nt = 0; nt < 4; nt++)
                    mma_tf32(acc[mt][nt], afr[mt][0], afr[mt][1], afr[mt][2], afr[mt][3],
                             bfr[nt][0], bfr[nt][1]);
        }
        if (++s == 3) s = 0;
    }

    if (!isKV) {
#pragma unroll
        for (int mt = 0; mt < 4; mt++) {
            const int row0 = rowBase + warpM * 64 + mt * 16 + g;
#pragma unroll
            for (int nt = 0; nt < 4; nt++) {
                const int c = colBase + warpN * 32 + nt * 8 + qd * 2;
                const float b0 = biasq[c], b1 = biasq[c + 1];
                float2 v0 = make_float2(acc[mt][nt][0] + b0, acc[mt][nt][1] + b1);
                float2 v1 = make_float2(acc[mt][nt][2] + b0, acc[mt][nt][3] + b1);
                *(float2*)&Cq[(size_t)row0 * Nq + c] = v0;
                *(float2*)&Cq[(size_t)(row0 + 8) * Nq + c] = v1;
            }
        }
    } else {
        // V half paired-scatter: Vh[gt][r>>1][n][r&1]
        auto wv = [&](int r, int n, float val) {
            int gt = r >> 6, rlo = r & 63;
            Cv[(((size_t)gt * 32 + (rlo >> 1)) * 64 + n) * 2 + (rlo & 1)] =
                __float2half_rn(val);
        };
#pragma unroll
        for (int mt = 0; mt < 4; mt++) {
            const int row0 = rowBase + warpM * 64 + mt * 16 + g;
#pragma unroll
            for (int nt = 0; nt < 4; nt++) {
                const int c = warpN * 32 + nt * 8 + qd * 2;
                if (c < 64) {
                    const float b0 = bk[c], b1 = bk[c + 1];
                    float2 v0 = make_float2(acc[mt][nt][0] + b0, acc[mt][nt][1] + b1);
                    float2 v1 = make_float2(acc[mt][nt][2] + b0, acc[mt][nt][3] + b1);
                    *(float2*)&Ck[(size_t)row0 * HD + c] = v0;
                    *(float2*)&Ck[(size_t)(row0 + 8) * HD + c] = v1;
                } else {
                    const int cv = c - 64;
                    const float b0 = bv[cv], b1 = bv[cv + 1];
                    wv(row0,     cv,     acc[mt][nt][0] + b0);
                    wv(row0,     cv + 1, acc[mt][nt][1] + b1);
                    wv(row0 + 8, cv,     acc[mt][nt][2] + b0);
                    wv(row0 + 8, cv + 1, acc[mt][nt][3] + b1);
                }
            }
        }
    }
}

// =========================================================================
// RoPE: q in-place (natural fp32); k natural -> half adjacent-d pair tiles.
// =========================================================================
__global__ void rope_kernel(float* __restrict__ q, const float* __restrict__ kin,
                            __half* __restrict__ k2out)
{
    const int total = BDIM*TDIM*(NH+1)*(HD/2);
    int idx = blockIdx.x*blockDim.x + threadIdx.x;
    if (idx >= total) return;
    int pr   = idx & 31;
    int rest = idx >> 5;
    int hh   = rest % (NH+1);
    int bt   = rest / (NH+1);
    int t    = bt & (TDIM-1);

    float inv_freq = expf(-(float)pr * (9.2103403719761836f / 32.0f));
    float ang = (float)t * inv_freq;
    float sn, cs;
    sincosf(ang, &sn, &cs);

    if (hh < NH) {
        float* base = q + (size_t)bt*CDIM + hh*HD;
        float t1 = base[pr];
        float t2 = base[pr + 32];
        base[pr]      = t1*cs + t2*sn;
        base[pr + 32] = t1*sn - t2*cs;
    } else {
        const float* base = kin + (size_t)bt*HD;
        float t1 = base[pr];
        float t2 = base[pr + 32];
        float v1 = t1*cs + t2*sn;      // element d1 = pr
        float v2 = t1*sn - t2*cs;      // element d2 = pr + 32
        int gt = bt >> 6, c = bt & 63;
        int d1 = pr, d2 = pr + 32;
        k2out[(((size_t)gt*32 + (d1>>1))*64 + c)*2 + (d1&1)] = __float2half_rn(v1);
        k2out[(((size_t)gt*32 + (d2>>1))*64 + c)*2 + (d2&1)] = __float2half_rn(v2);
    }
}

// =========================================================================
// fp16 tensor-core causal MQA flash attention.  BQ=BKV=64, HD=64.
// 128 threads = 4 warps x 16 q-rows. mma.m16n8k16.f16 (fp32 accum).
// K/V tiles arrive as half pairs via cp.async (8KB each, stride 72 half2
// in smem: bank = 8*qd+g, conflict-free fragment LDS).
// P stays in registers: m16n8k16 A-frag = two adjacent S C-frag n-tiles
// of the SAME thread -> zero shuffles, just f32->f16x2 packs.
// =========================================================================
#define KVS 72                        // K/V smem row stride (half2)
#define KTILE_H2 (32*KVS)             // 2304 half2 = 9216 B per tile
#define BUF_H2  (2*KTILE_H2)          // K+V per buffer = 18432 B
#define QS2 36                        // Q smem row stride (half2)
#define ATT_SMEM_BYTES (2*BUF_H2*4 + 64*QS2*4)   // 36864 + 9216 = 46080

__global__ void __launch_bounds__(128, 3)
attn_tc_kernel(const float* __restrict__ gq, const __half* __restrict__ gk2,
               const __half* __restrict__ gv2, float* __restrict__ go)
{
    extern __shared__ float sm[];
    const uint32_t sbase = smem_u32(sm);
    __half2*  QH2 = (__half2*)((char*)sm + 2*BUF_H2*4);
    const uint32_t* QU = (const uint32_t*)QH2;

    const int qtile = (gridDim.x - 1) - blockIdx.x;   // heavy blocks first
    const int h     = blockIdx.y;
    const int b     = blockIdx.z;
    const int tid   = threadIdx.x;
    const int lane  = tid & 31;
    const int w     = tid >> 5;
    const int g     = lane >> 2;
    const int qd    = lane & 3;
    const int r0    = w * 16;
    const int qbase = qtile * 64;
    const unsigned FULL = 0xffffffffu;

    // tile = 32 rows x 256B (gmem) -> 288B rows (smem); K+V = 8 chunks/thread
    auto issue_tile = [&](int t, int buf) {
        const char* kgb = (const char*)gk2 + (size_t)(b*32 + t) * 8192;
        const char* vgb = (const char*)gv2 + (size_t)(b*32 + t) * 8192;
        const uint32_t kb = sbase + buf * (BUF_H2 * 4);
        const uint32_t vb = kb + KTILE_H2 * 4;
#pragma unroll
        for (int i = 0; i < 4; i++) {
            int idx = tid + i * 128;            // 0..511
            int row = idx >> 4, ch = (idx & 15) << 4;
            CP_ASYNC16(kb + row * 288 + ch, kgb + row * 256 + ch);
            CP_ASYNC16(vb + row * 288 + ch, vgb + row * 256 + ch);
        }
        CP_COMMIT();
    };

    issue_tile(0, 0);

    // ---- stage Q (scaled 1/8) as half2 k-pairs ----
    {
        const float* qp = gq + ((size_t)(b*TDIM + qbase))*CDIM + h*HD;
#pragma unroll
        for (int i = 0; i < 8; i++) {
            int idx = tid + i*128;
            int r = idx >> 4, d4 = (idx & 15) << 2;
            float4 v = *(const float4*)(qp + (size_t)r*CDIM + d4);
            QH2[r*QS2 + (d4>>1)    ] = __floats2half2_rn(v.x*0.125f, v.y*0.125f);
            QH2[r*QS2 + (d4>>1) + 1] = __floats2half2_rn(v.z*0.125f, v.w*0.125f);
        }
    }
    __syncthreads();

    // ---- Q fragments in registers: aQ[kk][0..3] for mma kk (k=16kk..+15) ----
    uint32_t aQ[4][4];
#pragma unroll
    for (int kk = 0; kk < 4; kk++) {
        aQ[kk][0] = QU[(r0+g  )*QS2 + 8*kk + qd    ];
        aQ[kk][1] = QU[(r0+g+8)*QS2 + 8*kk + qd    ];
        aQ[kk][2] = QU[(r0+g  )*QS2 + 8*kk + qd + 4];
        aQ[kk][3] = QU[(r0+g+8)*QS2 + 8*kk + qd + 4];
    }

    float m_[2] = {-1e30f, -1e30f};
    float l_[2] = {0.0f, 0.0f};
    float oacc[8][4];
#pragma unroll
    for (int nt = 0; nt < 8; nt++)
#pragma unroll
        for (int i = 0; i < 4; i++) oacc[nt][i] = 0.0f;

    for (int t = 0; t <= qtile; t++) {
        const int buf = t & 1;

        CP_WAIT0();
        __syncthreads();

        if (t < qtile) issue_tile(t + 1, buf ^ 1);

        const uint32_t* KT = (const uint32_t*)sm + (size_t)buf * BUF_H2;
        const uint32_t* VT = KT + KTILE_H2;

        // ---- S = Q K^T  (4 k-chunks of 16) ----
        float sacc[8][4];
#pragma unroll
        for (int nt = 0; nt < 8; nt++)
#pragma unroll
            for (int i = 0; i < 4; i++) sacc[nt][i] = 0.0f;

#pragma unroll
        for (int kk = 0; kk < 4; kk++) {
            uint32_t b0[8], b1[8];
#pragma unroll
            for (int nt = 0; nt < 8; nt++) {
                b0[nt] = KT[(8*kk + qd    )*KVS + nt*8 + g];
                b1[nt] = KT[(8*kk + qd + 4)*KVS + nt*8 + g];
            }
#pragma unroll
            for (int nt = 0; nt < 8; nt++)
                mma_f16(sacc[nt], aQ[kk][0], aQ[kk][1], aQ[kk][2], aQ[kk][3],
                        b0[nt], b1[nt]);
        }

        // ---- causal mask (diagonal tile only) ----
        if (t == qtile) {
            const int ra = r0 + g, rb = ra + 8;
#pragma unroll
            for (int nt = 0; nt < 8; nt++) {
                const int ca = nt*8 + qd*2;
                if (ca     > ra) sacc[nt][0] = -1e30f;
                if (ca + 1 > ra) sacc[nt][1] = -1e30f;
                if (ca     > rb) sacc[nt][2] = -1e30f;
                if (ca + 1 > rb) sacc[nt][3] = -1e30f;
            }
        }

        // ---- online softmax; P packed to half2 in registers ----
        uint32_t pA[8], pB[8];   // pA[nt] = P(row g, cols 8nt+2qd..+1), pB = row g+8
#pragma unroll
        for (int rr = 0; rr < 2; rr++) {
            float lm = -1e30f;
#pragma unroll
            for (int nt = 0; nt < 8; nt++)
                lm = fmaxf(lm, fmaxf(sacc[nt][2*rr], sacc[nt][2*rr+1]));
            lm = fmaxf(lm, __shfl_xor_sync(FULL, lm, 1));
            lm = fmaxf(lm, __shfl_xor_sync(FULL, lm, 2));
            float mnew  = fmaxf(m_[rr], lm);
            float alpha = __expf(m_[rr] - mnew);

            float ls = 0.0f;
#pragma unroll
            for (int nt = 0; nt < 8; nt++) {
                float p0 = __expf(sacc[nt][2*rr]   - mnew);
                float p1 = __expf(sacc[nt][2*rr+1] - mnew);
                ls += p0 + p1;
                uint32_t pk = h2u(__floats2half2_rn(p0, p1));
                if (rr == 0) pA[nt] = pk; else pB[nt] = pk;
            }
            ls += __shfl_xor_sync(FULL, ls, 1);
            ls += __shfl_xor_sync(FULL, ls, 2);

            m_[rr] = mnew;
            l_[rr] = l_[rr]*alpha + ls;
#pragma unroll
            for (int nt = 0; nt < 8; nt++) {
                oacc[nt][2*rr]   *= alpha;
                oacc[nt][2*rr+1] *= alpha;
            }
        }

        // ---- O += P V : A-frag(kk) = {pA[2kk], pB[2kk], pA[2kk+1], pB[2kk+1]} ----
#pragma unroll
        for (int kk = 0; kk < 4; kk++) {
            uint32_t bv0[8], bv1[8];
#pragma unroll
            for (int nt = 0; nt < 8; nt++) {
                bv0[nt] = VT[(8*kk + qd    )*KVS + nt*8 + g];
                bv1[nt] = VT[(8*kk + qd + 4)*KVS + nt*8 + g];
            }
#pragma unroll
            for (int nt = 0; nt < 8; nt++)
                mma_f16(oacc[nt], pA[2*kk], pB[2*kk], pA[2*kk+1], pB[2*kk+1],
                        bv0[nt], bv1[nt]);
        }
    }

    // ---- normalize + store (tf32-prerounded for the Wo GEMM) ----
#pragma unroll
    for (int rr = 0; rr < 2; rr++) {
        const float inv = 1.0f / l_[rr];
        float* op = go + ((size_t)(b*TDIM + qbase + r0 + g + rr*8))*CDIM + h*HD;
#pragma unroll
        for (int nt = 0; nt < 8; nt++) {
            *(float2*)&op[nt*8 + qd*2] =
                make_float2(to_tf32(oacc[nt][2*rr]*inv), to_tf32(oacc[nt][2*rr+1]*inv));
        }
    }
}

// =========================================================================
// launch
// =========================================================================
extern "C" void kernel_launch(void* const* d_in, const int* in_sizes, int n_in,
                              void* d_out, int out_size)
{
    const float* x  = (const float*)d_in[0];
    const float* Wq = (const float*)d_in[1];
    const float* bq = (const float*)d_in[2];
    const float* Wk = (const float*)d_in[3];
    const float* bk = (const float*)d_in[4];
    const float* Wv = (const float*)d_in[5];
    const float* bv = (const float*)d_in[6];
    const float* Wo = (const float*)d_in[7];
    const float* bo = (const float*)d_in[8];
    float* out = (float*)d_out;

    float *qp, *kp, *ap;
    __half *k2p, *vp;
    cudaGetSymbolAddress((void**)&qp,  g_q);
    cudaGetSymbolAddress((void**)&kp,  g_k);
    cudaGetSymbolAddress((void**)&k2p, g_k2h);
    cudaGetSymbolAddress((void**)&vp,  g_vh);
    cudaGetSymbolAddress((void**)&ap,  g_att);

    cudaFuncSetAttribute(tc_gemm_fused_kernel,
        cudaFuncAttributeMaxDynamicSharedMemorySize, GP_SMEM);
    cudaFuncSetAttribute(attn_tc_kernel,
        cudaFuncAttributeMaxDynamicSharedMemorySize, ATT_SMEM_BYTES);

    // Q = x@Wq+bq  AND  K/V = x@[Wk|Wv]+b  in ONE launch (tile x==8 -> KV)
    tc_gemm_fused_kernel<<<dim3(9, MROWS/128), 256, GP_SMEM>>>(
        x, Wq, bq, qp,  Wk, bk, kp,  Wv, bv, vp);

    // RoPE: q in-place, k natural -> half pair tiles
    {
        int total = BDIM*TDIM*(NH+1)*(HD/2);
        rope_kernel<<<(total + 255)/256, 256>>>(qp, kp, k2p);
    }

    // causal MQA attention (fp16 m16n8k16)
    attn_tc_kernel<<<dim3(TDIM/64, NH, BDIM), 128, ATT_SMEM_BYTES>>>(
        qp, k2p, vp, ap);

    // out = att @ Wo + bo  (att pre-rounded; Wo rounded at frag load)
    tc_gemm_fused_kernel<<<dim3(8, MROWS/128), 256, GP_SMEM>>>(
        ap, Wo, bo, out,  Wk, bk, kp,  Wv, bv, vp);   // KV path unused (grid.x=8)
}

// round 15
// speedup vs baseline: 1.8605x; 1.1432x over previous
#include <cuda_runtime.h>
#include <cuda_fp16.h>
#include <math.h>
#include <cstdint>

// Problem dims (fixed)
#define BDIM 2
#define TDIM 2048
#define CDIM 1024
#define NH   16
#define HD   64
#define MROWS (BDIM*TDIM)   // 4096

// ---------------- device scratch (no allocations allowed) ----------------
__device__ float   g_q[(size_t)MROWS*CDIM];    // q after rope (fp32 natural)
__device__ float   g_k[(size_t)MROWS*HD];      // k pre-rope (fp32 natural)
__device__ __half  g_k2h[(size_t)MROWS*HD];    // k post-rope, half pair tiles
__device__ __half  g_vh[(size_t)MROWS*HD];     // v half pair tiles
__device__ __half  g_atth[(size_t)MROWS*CDIM]; // attn out, half natural
__device__ __half  g_xh[(size_t)MROWS*CDIM];   // x as half natural
__device__ __half2 g_wqp[(size_t)(CDIM/2)*CDIM];  // Wq row-pair half2 [512][1024]
__device__ __half2 g_wop[(size_t)(CDIM/2)*CDIM];  // Wo row-pair half2
__device__ __half2 g_wkvp[(size_t)(CDIM/2)*128];  // [Wk|Wv] row-pair half2 [512][128]

// ======================= helpers =========================================
__device__ __forceinline__ void mma_f16(float* c,
    uint32_t a0, uint32_t a1, uint32_t a2, uint32_t a3,
    uint32_t b0, uint32_t b1)
{
    asm volatile(
        "mma.sync.aligned.m16n8k16.row.col.f32.f16.f16.f32 "
        "{%0,%1,%2,%3}, {%4,%5,%6,%7}, {%8,%9}, {%0,%1,%2,%3};"
        : "+f"(c[0]), "+f"(c[1]), "+f"(c[2]), "+f"(c[3])
        : "r"(a0), "r"(a1), "r"(a2), "r"(a3), "r"(b0), "r"(b1));
}
__device__ __forceinline__ uint32_t h2u(__half2 h) {
    uint32_t u; *(__half2*)&u = h; return u;
}
__device__ __forceinline__ uint32_t smem_u32(const void* p) {
    uint32_t a;
    asm("{ .reg .u64 t; cvta.to.shared.u64 t, %1; cvt.u32.u64 %0, t; }"
        : "=r"(a) : "l"(p));
    return a;
}
#define CP_ASYNC16(dst_u32, src_ptr) \
    asm volatile("cp.async.cg.shared.global [%0], [%1], 16;" \
        :: "r"(dst_u32), "l"(src_ptr) : "memory")
#define CP_COMMIT() asm volatile("cp.async.commit_group;" ::: "memory")
#define CP_WAIT0()  asm volatile("cp.async.wait_group 0;"  ::: "memory")
#define CP_WAIT1()  asm volatile("cp.async.wait_group 1;"  ::: "memory")

// =========================================================================
// prep: fp32 -> half natural (8 elems/thread)
// =========================================================================
__global__ void f2h_kernel(const float4* __restrict__ in, uint4* __restrict__ out,
                           int n8)
{
    int i = blockIdx.x * blockDim.x + threadIdx.x;
    if (i >= n8) return;
    float4 a = in[2*i], b = in[2*i+1];
    uint4 o;
    o.x = h2u(__floats2half2_rn(a.x, a.y));
    o.y = h2u(__floats2half2_rn(a.z, a.w));
    o.z = h2u(__floats2half2_rn(b.x, b.y));
    o.w = h2u(__floats2half2_rn(b.z, b.w));
    out[i] = o;
}

// prep: W[K][N] fp32 -> Wp[K/2][N] half2 with pair (W[2p][n], W[2p+1][n]).
// N = 1024; thread per (p, n4).
__global__ void pairB_h_kernel(const float* __restrict__ W, uint4* __restrict__ Wp)
{
    int i = blockIdx.x * blockDim.x + threadIdx.x;   // < 512*256
    if (i >= 512*256) return;
    int n4 = i & 255, p = i >> 8;
    const float4 r0 = *(const float4*)&W[(size_t)(2*p  )*CDIM + n4*4];
    const float4 r1 = *(const float4*)&W[(size_t)(2*p+1)*CDIM + n4*4];
    uint4 o;
    o.x = h2u(__floats2half2_rn(r0.x, r1.x));
    o.y = h2u(__floats2half2_rn(r0.y, r1.y));
    o.z = h2u(__floats2half2_rn(r0.z, r1.z));
    o.w = h2u(__floats2half2_rn(r0.w, r1.w));
    *((uint4*)Wp + ((size_t)p*256 + n4)) = o;        // 1024 half2 per pair-row
}

// prep: Wk[1024][64], Wv[1024][64] -> Wkvp[512][128] half2 (cols 0-63 K, 64-127 V)
__global__ void pairKV_h_kernel(const float* __restrict__ Wk,
                                const float* __restrict__ Wv,
                                uint4* __restrict__ Wp)
{
    int i = blockIdx.x * blockDim.x + threadIdx.x;   // < 512*32
    if (i >= 512*32) return;
    int n4 = i & 15, z = (i >> 4) & 1, p = i >> 5;
    const float* src = z ? Wv : Wk;
    const float4 r0 = *(const float4*)&src[(size_t)(2*p  )*HD + n4*4];
    const float4 r1 = *(const float4*)&src[(size_t)(2*p+1)*HD + n4*4];
    uint4 o;
    o.x = h2u(__floats2half2_rn(r0.x, r1.x));
    o.y = h2u(__floats2half2_rn(r0.y, r1.y));
    o.z = h2u(__floats2half2_rn(r0.z, r1.z));
    o.w = h2u(__floats2half2_rn(r0.w, r1.w));
    *((uint4*)Wp + ((size_t)p*32 + z*16 + n4)) = o;  // 128 half2 per pair-row
}

// =========================================================================
// 3-stage cp.async pipelined fp16 GEMM (m16n8k16, fp32 accum):
//   C[M,N] = half(A)[M,K] @ half(B)[K,N] + bias[N]
// A: half natural [M][K].  Bp: row-pair half2 [K/2][N].
// BM=128, BN=128, BK=16, 256 threads = 8 warps (2m x 4n).
// Fused KV tile: gridDim.x==9 & blockIdx.x==8 -> x@[Wk|Wv] via Bkvp:
//   cols 0..63 -> K fp32 natural (Ck, +bk); 64..127 -> V half pair-scatter (Cv, +bv).
// =========================================================================
#define GH_AS2 12                      // A smem stride (half2): banks 12g+qd distinct
#define GH_BS2 136                     // B smem stride (half2): banks 8qd+g distinct
#define GH_ABYTES (128*GH_AS2*4)       // 6144
#define GH_BBYTES (8*GH_BS2*4)         // 4352
#define GH_STB (GH_ABYTES+GH_BBYTES)   // 10496 per stage
#define GH_SMEM (3*GH_STB)             // 31488

__global__ void __launch_bounds__(256)
hgemm_kernel(const __half* __restrict__ A,
             const __half2* __restrict__ Bp, const float* __restrict__ bias,
             float* __restrict__ Cq,
             const __half2* __restrict__ Bkvp,
             const float* __restrict__ bk, const float* __restrict__ bv,
             float* __restrict__ Ck, __half* __restrict__ Cv)
{
    constexpr int K = CDIM;
    extern __shared__ char smc[];
    const uint32_t sbase = smem_u32(smc);

    const bool isKV = (blockIdx.x == 8);
    const int  Nq   = CDIM;

    const int tid   = threadIdx.x;
    const int lane  = tid & 31;
    const int w     = tid >> 5;
    const int warpM = w & 1;
    const int warpN = w >> 1;
    const int g     = lane >> 2;
    const int qd    = lane & 3;
    const int rowBase = blockIdx.y * 128;
    const int colBase = isKV ? 0 : blockIdx.x * 128;

    // 2 cp.async 16B chunks/thread/stage: A=256 chunks, B=256 chunks
    const char* gsrc[2]; uint32_t soff[2]; size_t jstr[2];
#pragma unroll
    for (int i = 0; i < 2; i++) {
        int idx = tid + i * 256;
        if (idx < 256) {                       // A: row r, chunk c (8 halves)
            int r = idx >> 1, c = idx & 1;
            gsrc[i] = (const char*)(A + (size_t)(rowBase + r) * K) + c * 16;
            soff[i] = (uint32_t)(r * (GH_AS2*4) + c * 16);
            jstr[i] = 32;                      // 16 halves per j
        } else {                               // B: pair-row pr, chunk c (4 half2)
            int e = idx - 256;
            int pr = e >> 5, c = e & 31;
            const __half2* Bsel = isKV ? Bkvp : Bp;
            const int rowlen = isKV ? 128 : CDIM;   // half2 per pair-row
            gsrc[i] = (const char*)(Bsel + (size_t)pr * rowlen + colBase) + c * 16;
            soff[i] = (uint32_t)(GH_ABYTES + pr * (GH_BS2*4) + c * 16);
            jstr[i] = (size_t)8 * rowlen * 4;  // 8 pair-rows per j
        }
    }
    auto issue = [&](int j, int s) {
        const uint32_t sb = sbase + (uint32_t)s * GH_STB;
        CP_ASYNC16(sb + soff[0], gsrc[0] + (size_t)j * jstr[0]);
        CP_ASYNC16(sb + soff[1], gsrc[1] + (size_t)j * jstr[1]);
        CP_COMMIT();
    };

    const int NI = K / 16;   // 64

    float acc[4][4][4];
#pragma unroll
    for (int mt = 0; mt < 4; mt++)
#pragma unroll
        for (int nt = 0; nt < 4; nt++)
#pragma unroll
            for (int i = 0; i < 4; i++) acc[mt][nt][i] = 0.0f;

    issue(0, 0);
    issue(1, 1);

    int s = 0;
    for (int j = 0; j < NI; j++) {
        CP_WAIT1();
        __syncthreads();

        if (j + 2 < NI) {
            int s2 = s + 2; if (s2 >= 3) s2 -= 3;
            issue(j + 2, s2);
        } else {
            CP_COMMIT();   // empty group keeps wait_group accounting aligned
        }

        const uint32_t* Ah = (const uint32_t*)(smc + s * GH_STB);
        const uint32_t* Bh = (const uint32_t*)(smc + s * GH_STB + GH_ABYTES);

        uint32_t afr[4][4];
#pragma unroll
        for (int mt = 0; mt < 4; mt++) {
            const int m0 = warpM * 64 + mt * 16;
            afr[mt][0] = Ah[(m0 + g    ) * GH_AS2 + qd    ];
            afr[mt][1] = Ah[(m0 + g + 8) * GH_AS2 + qd    ];
            afr[mt][2] = Ah[(m0 + g    ) * GH_AS2 + qd + 4];
            afr[mt][3] = Ah[(m0 + g + 8) * GH_AS2 + qd + 4];
        }
        uint32_t bfr[4][2];
#pragma unroll
        for (int nt = 0; nt < 4; nt++) {
            const int n0 = warpN * 32 + nt * 8;
            bfr[nt][0] = Bh[(qd    ) * GH_BS2 + n0 + g];
            bfr[nt][1] = Bh[(qd + 4) * GH_BS2 + n0 + g];
        }
#pragma unroll
        for (int mt = 0; mt < 4; mt++)
#pragma unroll
            for (int nt = 0; nt < 4; nt++)
                mma_f16(acc[mt][nt], afr[mt][0], afr[mt][1], afr[mt][2], afr[mt][3],
                        bfr[nt][0], bfr[nt][1]);

        if (++s == 3) s = 0;
    }

    if (!isKV) {
#pragma unroll
        for (int mt = 0; mt < 4; mt++) {
            const int row0 = rowBase + warpM * 64 + mt * 16 + g;
#pragma unroll
            for (int nt = 0; nt < 4; nt++) {
                const int c = colBase + warpN * 32 + nt * 8 + qd * 2;
                const float b0 = bias[c], b1 = bias[c + 1];
                float2 v0 = make_float2(acc[mt][nt][0] + b0, acc[mt][nt][1] + b1);
                float2 v1 = make_float2(acc[mt][nt][2] + b0, acc[mt][nt][3] + b1);
                *(float2*)&Cq[(size_t)row0 * Nq + c] = v0;
                *(float2*)&Cq[(size_t)(row0 + 8) * Nq + c] = v1;
            }
        }
    } else {
        // V half pair-scatter: Vh[gt][r>>1][n][r&1]
        auto wv = [&](int r, int n, float val) {
            int gt = r >> 6, rlo = r & 63;
            Cv[(((size_t)gt * 32 + (rlo >> 1)) * 64 + n) * 2 + (rlo & 1)] =
                __float2half_rn(val);
        };
#pragma unroll
        for (int mt = 0; mt < 4; mt++) {
            const int row0 = rowBase + warpM * 64 + mt * 16 + g;
#pragma unroll
            for (int nt = 0; nt < 4; nt++) {
                const int c = warpN * 32 + nt * 8 + qd * 2;
                if (c < 64) {
                    const float b0 = bk[c], b1 = bk[c + 1];
                    float2 v0 = make_float2(acc[mt][nt][0] + b0, acc[mt][nt][1] + b1);
                    float2 v1 = make_float2(acc[mt][nt][2] + b0, acc[mt][nt][3] + b1);
                    *(float2*)&Ck[(size_t)row0 * HD + c] = v0;
                    *(float2*)&Ck[(size_t)(row0 + 8) * HD + c] = v1;
                } else {
                    const int cv = c - 64;
                    const float b0 = bv[cv], b1 = bv[cv + 1];
                    wv(row0,     cv,     acc[mt][nt][0] + b0);
                    wv(row0,     cv + 1, acc[mt][nt][1] + b1);
                    wv(row0 + 8, cv,     acc[mt][nt][2] + b0);
                    wv(row0 + 8, cv + 1, acc[mt][nt][3] + b1);
                }
            }
        }
    }
}

// =========================================================================
// RoPE: q in-place (fp32 natural); k fp32 natural -> half pair tiles.
// =========================================================================
__global__ void rope_kernel(float* __restrict__ q, const float* __restrict__ kin,
                            __half* __restrict__ k2out)
{
    const int total = BDIM*TDIM*(NH+1)*(HD/2);
    int idx = blockIdx.x*blockDim.x + threadIdx.x;
    if (idx >= total) return;
    int pr   = idx & 31;
    int rest = idx >> 5;
    int hh   = rest % (NH+1);
    int bt   = rest / (NH+1);
    int t    = bt & (TDIM-1);

    float inv_freq = expf(-(float)pr * (9.2103403719761836f / 32.0f));
    float ang = (float)t * inv_freq;
    float sn, cs;
    sincosf(ang, &sn, &cs);

    if (hh < NH) {
        float* base = q + (size_t)bt*CDIM + hh*HD;
        float t1 = base[pr];
        float t2 = base[pr + 32];
        base[pr]      = t1*cs + t2*sn;
        base[pr + 32] = t1*sn - t2*cs;
    } else {
        const float* base = kin + (size_t)bt*HD;
        float t1 = base[pr];
        float t2 = base[pr + 32];
        float v1 = t1*cs + t2*sn;      // element d1 = pr
        float v2 = t1*sn - t2*cs;      // element d2 = pr + 32
        int gt = bt >> 6, c = bt & 63;
        int d1 = pr, d2 = pr + 32;
        k2out[(((size_t)gt*32 + (d1>>1))*64 + c)*2 + (d1&1)] = __float2half_rn(v1);
        k2out[(((size_t)gt*32 + (d2>>1))*64 + c)*2 + (d2&1)] = __float2half_rn(v2);
    }
}

// =========================================================================
// fp16 tensor-core causal MQA flash attention (R14, measured best).
// Output: half natural (feeds the fp16 Wo GEMM directly).
// =========================================================================
#define KVS 72                        // K/V smem row stride (half2)
#define KTILE_H2 (32*KVS)             // 2304 half2 = 9216 B per tile
#define BUF_H2  (2*KTILE_H2)          // K+V per buffer = 18432 B
#define QS2 36                        // Q smem row stride (half2)
#define ATT_SMEM_BYTES (2*BUF_H2*4 + 64*QS2*4)   // 36864 + 9216 = 46080

__global__ void __launch_bounds__(128, 3)
attn_tc_kernel(const float* __restrict__ gq, const __half* __restrict__ gk2,
               const __half* __restrict__ gv2, __half* __restrict__ go)
{
    extern __shared__ float sm[];
    const uint32_t sbase = smem_u32(sm);
    __half2*  QH2 = (__half2*)((char*)sm + 2*BUF_H2*4);
    const uint32_t* QU = (const uint32_t*)QH2;

    const int qtile = (gridDim.x - 1) - blockIdx.x;   // heavy blocks first
    const int h     = blockIdx.y;
    const int b     = blockIdx.z;
    const int tid   = threadIdx.x;
    const int lane  = tid & 31;
    const int w     = tid >> 5;
    const int g     = lane >> 2;
    const int qd    = lane & 3;
    const int r0    = w * 16;
    const int qbase = qtile * 64;
    const unsigned FULL = 0xffffffffu;

    auto issue_tile = [&](int t, int buf) {
        const char* kgb = (const char*)gk2 + (size_t)(b*32 + t) * 8192;
        const char* vgb = (const char*)gv2 + (size_t)(b*32 + t) * 8192;
        const uint32_t kb = sbase + buf * (BUF_H2 * 4);
        const uint32_t vb = kb + KTILE_H2 * 4;
#pragma unroll
        for (int i = 0; i < 4; i++) {
            int idx = tid + i * 128;
            int row = idx >> 4, ch = (idx & 15) << 4;
            CP_ASYNC16(kb + row * 288 + ch, kgb + row * 256 + ch);
            CP_ASYNC16(vb + row * 288 + ch, vgb + row * 256 + ch);
        }
        CP_COMMIT();
    };

    issue_tile(0, 0);

    // ---- stage Q (scaled 1/8) as half2 k-pairs ----
    {
        const float* qp = gq + ((size_t)(b*TDIM + qbase))*CDIM + h*HD;
#pragma unroll
        for (int i = 0; i < 8; i++) {
            int idx = tid + i*128;
            int r = idx >> 4, d4 = (idx & 15) << 2;
            float4 v = *(const float4*)(qp + (size_t)r*CDIM + d4);
            QH2[r*QS2 + (d4>>1)    ] = __floats2half2_rn(v.x*0.125f, v.y*0.125f);
            QH2[r*QS2 + (d4>>1) + 1] = __floats2half2_rn(v.z*0.125f, v.w*0.125f);
        }
    }
    __syncthreads();

    uint32_t aQ[4][4];
#pragma unroll
    for (int kk = 0; kk < 4; kk++) {
        aQ[kk][0] = QU[(r0+g  )*QS2 + 8*kk + qd    ];
        aQ[kk][1] = QU[(r0+g+8)*QS2 + 8*kk + qd    ];
        aQ[kk][2] = QU[(r0+g  )*QS2 + 8*kk + qd + 4];
        aQ[kk][3] = QU[(r0+g+8)*QS2 + 8*kk + qd + 4];
    }

    float m_[2] = {-1e30f, -1e30f};
    float l_[2] = {0.0f, 0.0f};
    float oacc[8][4];
#pragma unroll
    for (int nt = 0; nt < 8; nt++)
#pragma unroll
        for (int i = 0; i < 4; i++) oacc[nt][i] = 0.0f;

    for (int t = 0; t <= qtile; t++) {
        const int buf = t & 1;

        CP_WAIT0();
        __syncthreads();

        if (t < qtile) issue_tile(t + 1, buf ^ 1);

        const uint32_t* KT = (const uint32_t*)sm + (size_t)buf * BUF_H2;
        const uint32_t* VT = KT + KTILE_H2;

        // ---- S = Q K^T ----
        float sacc[8][4];
#pragma unroll
        for (int nt = 0; nt < 8; nt++)
#pragma unroll
            for (int i = 0; i < 4; i++) sacc[nt][i] = 0.0f;

#pragma unroll
        for (int kk = 0; kk < 4; kk++) {
            uint32_t b0[8], b1[8];
#pragma unroll
            for (int nt = 0; nt < 8; nt++) {
                b0[nt] = KT[(8*kk + qd    )*KVS + nt*8 + g];
                b1[nt] = KT[(8*kk + qd + 4)*KVS + nt*8 + g];
            }
#pragma unroll
            for (int nt = 0; nt < 8; nt++)
                mma_f16(sacc[nt], aQ[kk][0], aQ[kk][1], aQ[kk][2], aQ[kk][3],
                        b0[nt], b1[nt]);
        }

        // ---- causal mask (diagonal tile only) ----
        if (t == qtile) {
            const int ra = r0 + g, rb = ra + 8;
#pragma unroll
            for (int nt = 0; nt < 8; nt++) {
                const int ca = nt*8 + qd*2;
                if (ca     > ra) sacc[nt][0] = -1e30f;
                if (ca + 1 > ra) sacc[nt][1] = -1e30f;
                if (ca     > rb) sacc[nt][2] = -1e30f;
                if (ca + 1 > rb) sacc[nt][3] = -1e30f;
            }
        }

        // ---- online softmax; P packed to half2 in registers ----
        uint32_t pA[8], pB[8];
#pragma unroll
        for (int rr = 0; rr < 2; rr++) {
            float lm = -1e30f;
#pragma unroll
            for (int nt = 0; nt < 8; nt++)
                lm = fmaxf(lm, fmaxf(sacc[nt][2*rr], sacc[nt][2*rr+1]));
            lm = fmaxf(lm, __shfl_xor_sync(FULL, lm, 1));
            lm = fmaxf(lm, __shfl_xor_sync(FULL, lm, 2));
            float mnew  = fmaxf(m_[rr], lm);
            float alpha = __expf(m_[rr] - mnew);

            float ls = 0.0f;
#pragma unroll
            for (int nt = 0; nt < 8; nt++) {
                float p0 = __expf(sacc[nt][2*rr]   - mnew);
                float p1 = __expf(sacc[nt][2*rr+1] - mnew);
                ls += p0 + p1;
                uint32_t pk = h2u(__floats2half2_rn(p0, p1));
                if (rr == 0) pA[nt] = pk; else pB[nt] = pk;
            }
            ls += __shfl_xor_sync(FULL, ls, 1);
            ls += __shfl_xor_sync(FULL, ls, 2);

            m_[rr] = mnew;
            l_[rr] = l_[rr]*alpha + ls;
#pragma unroll
            for (int nt = 0; nt < 8; nt++) {
                oacc[nt][2*rr]   *= alpha;
                oacc[nt][2*rr+1] *= alpha;
            }
        }

        // ---- O += P V ----
#pragma unroll
        for (int kk = 0; kk < 4; kk++) {
            uint32_t bv0[8], bv1[8];
#pragma unroll
            for (int nt = 0; nt < 8; nt++) {
                bv0[nt] = VT[(8*kk + qd    )*KVS + nt*8 + g];
                bv1[nt] = VT[(8*kk + qd + 4)*KVS + nt*8 + g];
            }
#pragma unroll
            for (int nt = 0; nt < 8; nt++)
                mma_f16(oacc[nt], pA[2*kk], pB[2*kk], pA[2*kk+1], pB[2*kk+1],
                        bv0[nt], bv1[nt]);
        }
    }

    // ---- normalize + store as half natural ----
#pragma unroll
    for (int rr = 0; rr < 2; rr++) {
        const float inv = 1.0f / l_[rr];
        __half2* op = (__half2*)(go + ((size_t)(b*TDIM + qbase + r0 + g + rr*8))*CDIM + h*HD);
#pragma unroll
        for (int nt = 0; nt < 8; nt++) {
            op[nt*4 + qd] =
                __floats2half2_rn(oacc[nt][2*rr]*inv, oacc[nt][2*rr+1]*inv);
        }
    }
}

// =========================================================================
// launch
// =========================================================================
extern "C" void kernel_launch(void* const* d_in, const int* in_sizes, int n_in,
                              void* d_out, int out_size)
{
    const float* x  = (const float*)d_in[0];
    const float* Wq = (const float*)d_in[1];
    const float* bq = (const float*)d_in[2];
    const float* Wk = (const float*)d_in[3];
    const float* bk = (const float*)d_in[4];
    const float* Wv = (const float*)d_in[5];
    const float* bv = (const float*)d_in[6];
    const float* Wo = (const float*)d_in[7];
    const float* bo = (const float*)d_in[8];
    float* out = (float*)d_out;

    float *qp, *kp;
    __half *k2p, *vp, *ap, *xh;
    __half2 *wqp, *wop, *wkvp;
    cudaGetSymbolAddress((void**)&qp,   g_q);
    cudaGetSymbolAddress((void**)&kp,   g_k);
    cudaGetSymbolAddress((void**)&k2p,  g_k2h);
    cudaGetSymbolAddress((void**)&vp,   g_vh);
    cudaGetSymbolAddress((void**)&ap,   g_atth);
    cudaGetSymbolAddress((void**)&xh,   g_xh);
    cudaGetSymbolAddress((void**)&wqp,  g_wqp);
    cudaGetSymbolAddress((void**)&wop,  g_wop);
    cudaGetSymbolAddress((void**)&wkvp, g_wkvp);

    cudaFuncSetAttribute(hgemm_kernel,
        cudaFuncAttributeMaxDynamicSharedMemorySize, GH_SMEM);
    cudaFuncSetAttribute(attn_tc_kernel,
        cudaFuncAttributeMaxDynamicSharedMemorySize, ATT_SMEM_BYTES);

    // prep: x -> half natural; Wq/Wo -> row-pair half2; [Wk|Wv] -> row-pair half2
    {
        int n8 = MROWS*CDIM/8;
        f2h_kernel<<<(n8 + 255)/256, 256>>>((const float4*)x, (uint4*)xh, n8);
        pairB_h_kernel<<<(512*256 + 255)/256, 256>>>(Wq, (uint4*)wqp);
        pairB_h_kernel<<<(512*256 + 255)/256, 256>>>(Wo, (uint4*)wop);
        pairKV_h_kernel<<<(512*32 + 255)/256, 256>>>(Wk, Wv, (uint4*)wkvp);
    }

    // Q = x@Wq+bq  AND  K/V = x@[Wk|Wv]+b  in ONE fp16 launch (tile x==8 -> KV)
    hgemm_kernel<<<dim3(9, MROWS/128), 256, GH_SMEM>>>(
        xh, wqp, bq, qp,  wkvp, bk, bv, kp, vp);

    // RoPE: q in-place, k natural -> half pair tiles
    {
        int total = BDIM*TDIM*(NH+1)*(HD/2);
        rope_kernel<<<(total + 255)/256, 256>>>(qp, kp, k2p);
    }

    // causal MQA attention (fp16 m16n8k16) -> half natural att
    attn_tc_kernel<<<dim3(TDIM/64, NH, BDIM), 128, ATT_SMEM_BYTES>>>(
        qp, k2p, vp, ap);

    // out = att @ Wo + bo  (fp16 GEMM; att already half)
    hgemm_kernel<<<dim3(8, MROWS/128), 256, GH_SMEM>>>(
        ap, wop, bo, out,  wkvp, bk, bv, kp, vp);   // KV path unused (grid.x=8)
}

// round 16
// speedup vs baseline: 2.0963x; 1.1267x over previous
#include <cuda_runtime.h>
#include <cuda_fp16.h>
#include <math.h>
#include <cstdint>

// Problem dims (fixed)
#define BDIM 2
#define TDIM 2048
#define CDIM 1024
#define NH   16
#define HD   64
#define MROWS (BDIM*TDIM)   // 4096

// ---------------- device scratch (no allocations allowed) ----------------
__device__ float   g_q[(size_t)MROWS*CDIM];    // q after rope (fp32 natural)
__device__ float   g_k[(size_t)MROWS*HD];      // k pre-rope (fp32 natural)
__device__ __half  g_k2h[(size_t)MROWS*HD];    // k post-rope, quad-pair tiles
__device__ __half  g_vh[(size_t)MROWS*HD];     // v quad-pair tiles
__device__ __half  g_atth[(size_t)MROWS*CDIM]; // attn out, half, k-group PERMUTED
__device__ __half  g_xh[(size_t)MROWS*CDIM];   // x half, k-group PERMUTED
__device__ uint2   g_wqp[(size_t)256*CDIM];    // Wq quad-pair u2 [256][1024]
__device__ uint2   g_wop[(size_t)256*CDIM];    // Wo quad-pair u2
__device__ uint2   g_wkvp[(size_t)256*128];    // [Wk|Wv] quad-pair u2 [256][128]

// A-side permuted layout: within each 16-half k-group, half2 j stored at
//   pos(j) = 2*(j&3) + (j>>2)   i.e. order [j0,j4,j1,j5,j2,j6,j3,j7]
//   -> (a0,a2) at u2 index qd of the group; (a1,a3) likewise on row g+8.
// B-side quad-pair layout: row pq = 4*kk + qd holds, per col n, uint2
//   { h2(B[k0][n],B[k0+1][n]), h2(B[k0+8][n],B[k0+9][n]) },  k0 = 16kk+2qd
//   -> (b0,b1) = one uint2.
// K/V tiles (per 64-row kv tile gt): same quad-pair structure, 16 rows x 64 u2.

// ======================= helpers =========================================
__device__ __forceinline__ void mma_f16(float* c,
    uint32_t a0, uint32_t a1, uint32_t a2, uint32_t a3,
    uint32_t b0, uint32_t b1)
{
    asm volatile(
        "mma.sync.aligned.m16n8k16.row.col.f32.f16.f16.f32 "
        "{%0,%1,%2,%3}, {%4,%5,%6,%7}, {%8,%9}, {%0,%1,%2,%3};"
        : "+f"(c[0]), "+f"(c[1]), "+f"(c[2]), "+f"(c[3])
        : "r"(a0), "r"(a1), "r"(a2), "r"(a3), "r"(b0), "r"(b1));
}
__device__ __forceinline__ uint32_t h2u(__half2 h) {
    uint32_t u; *(__half2*)&u = h; return u;
}
__device__ __forceinline__ uint32_t smem_u32(const void* p) {
    uint32_t a;
    asm("{ .reg .u64 t; cvta.to.shared.u64 t, %1; cvt.u32.u64 %0, t; }"
        : "=r"(a) : "l"(p));
    return a;
}
#define CP_ASYNC16(dst_u32, src_ptr) \
    asm volatile("cp.async.cg.shared.global [%0], [%1], 16;" \
        :: "r"(dst_u32), "l"(src_ptr) : "memory")
#define CP_COMMIT() asm volatile("cp.async.commit_group;" ::: "memory")
#define CP_WAIT0()  asm volatile("cp.async.wait_group 0;"  ::: "memory")
#define CP_WAIT1()  asm volatile("cp.async.wait_group 1;"  ::: "memory")

// =========================================================================
// prep: fp32 -> half with per-16-group A permutation. Thread per k16 group.
// =========================================================================
__global__ void f2h_perm_kernel(const float4* __restrict__ in,
                                uint4* __restrict__ out, int ngroups)
{
    int i = blockIdx.x * blockDim.x + threadIdx.x;
    if (i >= ngroups) return;
    float4 f0 = in[i*4+0], f1 = in[i*4+1], f2 = in[i*4+2], f3 = in[i*4+3];
    uint4 o0, o1;
    o0.x = h2u(__floats2half2_rn(f0.x, f0.y));   // j0
    o0.y = h2u(__floats2half2_rn(f2.x, f2.y));   // j4
    o0.z = h2u(__floats2half2_rn(f0.z, f0.w));   // j1
    o0.w = h2u(__floats2half2_rn(f2.z, f2.w));   // j5
    o1.x = h2u(__floats2half2_rn(f1.x, f1.y));   // j2
    o1.y = h2u(__floats2half2_rn(f3.x, f3.y));   // j6
    o1.z = h2u(__floats2half2_rn(f1.z, f1.w));   // j3
    o1.w = h2u(__floats2half2_rn(f3.z, f3.w));   // j7
    out[i*2]   = o0;
    out[i*2+1] = o1;
}

// prep: W[1024][1024] -> quad-pair u2 [256][1024]. Thread per (pq, n4).
__global__ void pairB2_kernel(const float* __restrict__ W, uint4* __restrict__ Wp)
{
    int i = blockIdx.x * blockDim.x + threadIdx.x;   // < 256*256
    if (i >= 256*256) return;
    int n4 = i & 255, pq = i >> 8;
    int k0 = (pq >> 2) * 16 + (pq & 3) * 2;
    const float4 a = *(const float4*)&W[(size_t)(k0    )*CDIM + n4*4];
    const float4 b = *(const float4*)&W[(size_t)(k0 + 1)*CDIM + n4*4];
    const float4 c = *(const float4*)&W[(size_t)(k0 + 8)*CDIM + n4*4];
    const float4 d = *(const float4*)&W[(size_t)(k0 + 9)*CDIM + n4*4];
    uint4 oA, oB;
    oA.x = h2u(__floats2half2_rn(a.x, b.x)); oA.y = h2u(__floats2half2_rn(c.x, d.x));
    oA.z = h2u(__floats2half2_rn(a.y, b.y)); oA.w = h2u(__floats2half2_rn(c.y, d.y));
    oB.x = h2u(__floats2half2_rn(a.z, b.z)); oB.y = h2u(__floats2half2_rn(c.z, d.z));
    oB.z = h2u(__floats2half2_rn(a.w, b.w)); oB.w = h2u(__floats2half2_rn(c.w, d.w));
    uint4* dst = (uint4*)Wp + ((size_t)pq * 512 + n4 * 2);
    dst[0] = oA; dst[1] = oB;
}

// prep: Wk/Wv [1024][64] -> quad-pair u2 [256][128] (cols 0-63 K, 64-127 V)
__global__ void pairKV2_kernel(const float* __restrict__ Wk,
                               const float* __restrict__ Wv,
                               uint4* __restrict__ Wp)
{
    int i = blockIdx.x * blockDim.x + threadIdx.x;   // < 256*2*16
    if (i >= 256*32) return;
    int n4 = i & 15, z = (i >> 4) & 1, pq = i >> 5;
    int k0 = (pq >> 2) * 16 + (pq & 3) * 2;
    const float* src = z ? Wv : Wk;
    const float4 a = *(const float4*)&src[(size_t)(k0    )*HD + n4*4];
    const float4 b = *(const float4*)&src[(size_t)(k0 + 1)*HD + n4*4];
    const float4 c = *(const float4*)&src[(size_t)(k0 + 8)*HD + n4*4];
    const float4 d = *(const float4*)&src[(size_t)(k0 + 9)*HD + n4*4];
    uint4 oA, oB;
    oA.x = h2u(__floats2half2_rn(a.x, b.x)); oA.y = h2u(__floats2half2_rn(c.x, d.x));
    oA.z = h2u(__floats2half2_rn(a.y, b.y)); oA.w = h2u(__floats2half2_rn(c.y, d.y));
    oB.x = h2u(__floats2half2_rn(a.z, b.z)); oB.y = h2u(__floats2half2_rn(c.z, d.z));
    oB.z = h2u(__floats2half2_rn(a.w, b.w)); oB.w = h2u(__floats2half2_rn(c.w, d.w));
    uint4* dst = (uint4*)Wp + ((size_t)pq * 64 + z * 32 + n4 * 2);
    dst[0] = oA; dst[1] = oB;
}

// =========================================================================
// 3-stage cp.async pipelined fp16 GEMM, ALL fragment loads LDS.64:
//   C[M,N] = A[M,K] @ B[K,N] + bias[N]
// A: permuted half; B: quad-pair u2 rows. BM=128, BN=128, BK=16, 8 warps.
// Fused KV tile (gridDim.x==9, blockIdx.x==8): x@[Wk|Wv] via Bkvp.
// =========================================================================
#define GH_ABYTES (128*32)             // A stage: 128 rows x 32B, no pad
#define GH_BS_U2  132                  // B stage row stride (u2)
#define GH_BBYTES (4*GH_BS_U2*8)       // 4224
#define GH_STB (GH_ABYTES+GH_BBYTES)   // 8320 per stage
#define GH_SMEM (3*GH_STB)             // 24960

__global__ void __launch_bounds__(256)
hgemm_kernel(const __half* __restrict__ A,
             const uint2* __restrict__ Bp, const float* __restrict__ bias,
             float* __restrict__ Cq,
             const uint2* __restrict__ Bkvp,
             const float* __restrict__ bk, const float* __restrict__ bv,
             float* __restrict__ Ck, __half* __restrict__ Cv)
{
    constexpr int K = CDIM;
    extern __shared__ char smc[];
    const uint32_t sbase = smem_u32(smc);

    const bool isKV = (blockIdx.x == 8);
    const int  Nq   = CDIM;

    const int tid   = threadIdx.x;
    const int lane  = tid & 31;
    const int w     = tid >> 5;
    const int warpM = w & 1;
    const int warpN = w >> 1;
    const int g     = lane >> 2;
    const int qd    = lane & 3;
    const int rowBase = blockIdx.y * 128;
    const int colBase = isKV ? 0 : blockIdx.x * 128;

    // 2 cp.async 16B chunks/thread/stage: A=256 chunks, B=256 chunks
    const char* gsrc[2]; uint32_t soff[2]; size_t jstr[2];
#pragma unroll
    for (int i = 0; i < 2; i++) {
        int idx = tid + i * 256;
        if (idx < 256) {                       // A: row r, chunk c
            int r = idx >> 1, c = idx & 1;
            gsrc[i] = (const char*)(A + (size_t)(rowBase + r) * K) + c * 16;
            soff[i] = (uint32_t)(r * 32 + c * 16);
            jstr[i] = 32;                      // 16 halves per j
        } else {                               // B: quad row pr, chunk c
            int e = idx - 256;
            int pr = e >> 6, c = e & 63;
            const uint2* Bsel = isKV ? Bkvp : Bp;
            const int rowlen = isKV ? 128 : CDIM;   // u2 per quad row
            gsrc[i] = (const char*)(Bsel + (size_t)pr * rowlen + colBase) + c * 16;
            soff[i] = (uint32_t)(GH_ABYTES + pr * (GH_BS_U2*8) + c * 16);
            jstr[i] = (size_t)4 * rowlen * 8;  // 4 quad rows per j
        }
    }
    auto issue = [&](int j, int s) {
        const uint32_t sb = sbase + (uint32_t)s * GH_STB;
        CP_ASYNC16(sb + soff[0], gsrc[0] + (size_t)j * jstr[0]);
        CP_ASYNC16(sb + soff[1], gsrc[1] + (size_t)j * jstr[1]);
        CP_COMMIT();
    };

    const int NI = K / 16;   // 64

    float acc[4][4][4];
#pragma unroll
    for (int mt = 0; mt < 4; mt++)
#pragma unroll
        for (int nt = 0; nt < 4; nt++)
#pragma unroll
            for (int i = 0; i < 4; i++) acc[mt][nt][i] = 0.0f;

    issue(0, 0);
    issue(1, 1);

    int s = 0;
    for (int j = 0; j < NI; j++) {
        CP_WAIT1();
        __syncthreads();

        if (j + 2 < NI) {
            int s2 = s + 2; if (s2 >= 3) s2 -= 3;
            issue(j + 2, s2);
        } else {
            CP_COMMIT();   // empty group keeps wait_group accounting aligned
        }

        const uint2* Ah = (const uint2*)(smc + s * GH_STB);
        const uint2* Bh = (const uint2*)(smc + s * GH_STB + GH_ABYTES);

        uint2 af[4][2];
#pragma unroll
        for (int mt = 0; mt < 4; mt++) {
            const int m0 = warpM * 64 + mt * 16;
            af[mt][0] = Ah[(m0 + g    ) * 4 + qd];   // {a0, a2}
            af[mt][1] = Ah[(m0 + g + 8) * 4 + qd];   // {a1, a3}
        }
        uint2 bf[4];
#pragma unroll
        for (int nt = 0; nt < 4; nt++) {
            const int n0 = warpN * 32 + nt * 8;
            bf[nt] = Bh[qd * GH_BS_U2 + n0 + g];     // {b0, b1}
        }
#pragma unroll
        for (int mt = 0; mt < 4; mt++)
#pragma unroll
            for (int nt = 0; nt < 4; nt++)
                mma_f16(acc[mt][nt], af[mt][0].x, af[mt][1].x,
                        af[mt][0].y, af[mt][1].y, bf[nt].x, bf[nt].y);

        if (++s == 3) s = 0;
    }

    if (!isKV) {
#pragma unroll
        for (int mt = 0; mt < 4; mt++) {
            const int row0 = rowBase + warpM * 64 + mt * 16 + g;
#pragma unroll
            for (int nt = 0; nt < 4; nt++) {
                const int c = colBase + warpN * 32 + nt * 8 + qd * 2;
                const float b0 = bias[c], b1 = bias[c + 1];
                float2 v0 = make_float2(acc[mt][nt][0] + b0, acc[mt][nt][1] + b1);
                float2 v1 = make_float2(acc[mt][nt][2] + b0, acc[mt][nt][3] + b1);
                *(float2*)&Cq[(size_t)row0 * Nq + c] = v0;
                *(float2*)&Cq[(size_t)(row0 + 8) * Nq + c] = v1;
            }
        }
    } else {
        // V quad-pair scatter
        auto wv = [&](int r, int n, float val) {
            int gt = r >> 6, rlo = r & 63;
            int kk = rlo >> 4, ww = rlo & 15, hh = ww & 1, rest = ww >> 1;
            int qd2 = rest & 3, comp = rest >> 2;
            Cv[(((size_t)gt*16 + 4*kk + qd2) * 64 + n) * 4 + comp*2 + hh] =
                __float2half_rn(val);
        };
#pragma unroll
        for (int mt = 0; mt < 4; mt++) {
            const int row0 = rowBase + warpM * 64 + mt * 16 + g;
#pragma unroll
            for (int nt = 0; nt < 4; nt++) {
                const int c = warpN * 32 + nt * 8 + qd * 2;
                if (c < 64) {
                    const float b0 = bk[c], b1 = bk[c + 1];
                    float2 v0 = make_float2(acc[mt][nt][0] + b0, acc[mt][nt][1] + b1);
                    float2 v1 = make_float2(acc[mt][nt][2] + b0, acc[mt][nt][3] + b1);
                    *(float2*)&Ck[(size_t)row0 * HD + c] = v0;
                    *(float2*)&Ck[(size_t)(row0 + 8) * HD + c] = v1;
                } else {
                    const int cv = c - 64;
                    const float b0 = bv[cv], b1 = bv[cv + 1];
                    wv(row0,     cv,     acc[mt][nt][0] + b0);
                    wv(row0,     cv + 1, acc[mt][nt][1] + b1);
                    wv(row0 + 8, cv,     acc[mt][nt][2] + b0);
                    wv(row0 + 8, cv + 1, acc[mt][nt][3] + b1);
                }
            }
        }
    }
}

// =========================================================================
// RoPE: q in-place (fp32); k -> half quad-pair tiles.
// =========================================================================
__global__ void rope_kernel(float* __restrict__ q, const float* __restrict__ kin,
                            __half* __restrict__ k2out)
{
    const int total = BDIM*TDIM*(NH+1)*(HD/2);
    int idx = blockIdx.x*blockDim.x + threadIdx.x;
    if (idx >= total) return;
    int pr   = idx & 31;
    int rest = idx >> 5;
    int hh   = rest % (NH+1);
    int bt   = rest / (NH+1);
    int t    = bt & (TDIM-1);

    float inv_freq = expf(-(float)pr * (9.2103403719761836f / 32.0f));
    float ang = (float)t * inv_freq;
    float sn, cs;
    sincosf(ang, &sn, &cs);

    if (hh < NH) {
        float* base = q + (size_t)bt*CDIM + hh*HD;
        float t1 = base[pr];
        float t2 = base[pr + 32];
        base[pr]      = t1*cs + t2*sn;
        base[pr + 32] = t1*sn - t2*cs;
    } else {
        const float* base = kin + (size_t)bt*HD;
        float t1 = base[pr];
        float t2 = base[pr + 32];
        float v1 = t1*cs + t2*sn;      // element d1 = pr
        float v2 = t1*sn - t2*cs;      // element d2 = pr + 32
        int gt = bt >> 6, c = bt & 63;
        auto put = [&](int d, float val) {
            int kk = d >> 4, ww = d & 15, h = ww & 1, rr = ww >> 1;
            int qd2 = rr & 3, comp = rr >> 2;
            k2out[(((size_t)gt*16 + 4*kk + qd2)*64 + c)*4 + comp*2 + h] =
                __float2half_rn(val);
        };
        put(pr, v1);
        put(pr + 32, v2);
    }
}

// =========================================================================
// fp16 tensor-core causal MQA flash attention, LDS.64 K/V fragment loads.
// Output: half, A-permuted k-groups (feeds the Wo hgemm directly).
// =========================================================================
#define KVS_U2 68                     // K/V smem row stride (uint2)
#define KTILE_U2 (16*KVS_U2)          // 1088 u2 = 8704 B per tile
#define BUF_U2  (2*KTILE_U2)          // K+V per buffer = 17408 B
#define QS2 36                        // Q smem row stride (half2)
#define ATT_SMEM_BYTES (2*BUF_U2*8 + 64*QS2*4)   // 34816 + 9216 = 44032

__global__ void __launch_bounds__(128, 3)
attn_tc_kernel(const float* __restrict__ gq, const __half* __restrict__ gk2,
               const __half* __restrict__ gv2, __half* __restrict__ go)
{
    extern __shared__ float sm[];
    const uint32_t sbase = smem_u32(sm);
    __half2*  QH2 = (__half2*)((char*)sm + 2*BUF_U2*8);
    const uint32_t* QU = (const uint32_t*)QH2;

    const int qtile = (gridDim.x - 1) - blockIdx.x;   // heavy blocks first
    const int h     = blockIdx.y;
    const int b     = blockIdx.z;
    const int tid   = threadIdx.x;
    const int lane  = tid & 31;
    const int w     = tid >> 5;
    const int g     = lane >> 2;
    const int qd    = lane & 3;
    const int r0    = w * 16;
    const int qbase = qtile * 64;
    const unsigned FULL = 0xffffffffu;

    // tile = 16 rows x 512B (gmem) -> 544B rows (smem); K+V = 8 chunks/thread
    auto issue_tile = [&](int t, int buf) {
        const char* kgb = (const char*)gk2 + (size_t)(b*32 + t) * 8192;
        const char* vgb = (const char*)gv2 + (size_t)(b*32 + t) * 8192;
        const uint32_t kb = sbase + buf * (BUF_U2 * 8);
        const uint32_t vb = kb + KTILE_U2 * 8;
#pragma unroll
        for (int i = 0; i < 4; i++) {
            int idx = tid + i * 128;            // 0..511
            int row = idx >> 5, ch = (idx & 31) << 4;
            CP_ASYNC16(kb + row * 544 + ch, kgb + row * 512 + ch);
            CP_ASYNC16(vb + row * 544 + ch, vgb + row * 512 + ch);
        }
        CP_COMMIT();
    };

    issue_tile(0, 0);

    // ---- stage Q (scaled 1/8) as half2 k-pairs (natural order) ----
    {
        const float* qp = gq + ((size_t)(b*TDIM + qbase))*CDIM + h*HD;
#pragma unroll
        for (int i = 0; i < 8; i++) {
            int idx = tid + i*128;
            int r = idx >> 4, d4 = (idx & 15) << 2;
            float4 v = *(const float4*)(qp + (size_t)r*CDIM + d4);
            QH2[r*QS2 + (d4>>1)    ] = __floats2half2_rn(v.x*0.125f, v.y*0.125f);
            QH2[r*QS2 + (d4>>1) + 1] = __floats2half2_rn(v.z*0.125f, v.w*0.125f);
        }
    }
    __syncthreads();

    uint32_t aQ[4][4];
#pragma unroll
    for (int kk = 0; kk < 4; kk++) {
        aQ[kk][0] = QU[(r0+g  )*QS2 + 8*kk + qd    ];
        aQ[kk][1] = QU[(r0+g+8)*QS2 + 8*kk + qd    ];
        aQ[kk][2] = QU[(r0+g  )*QS2 + 8*kk + qd + 4];
        aQ[kk][3] = QU[(r0+g+8)*QS2 + 8*kk + qd + 4];
    }

    float m_[2] = {-1e30f, -1e30f};
    float l_[2] = {0.0f, 0.0f};
    float oacc[8][4];
#pragma unroll
    for (int nt = 0; nt < 8; nt++)
#pragma unroll
        for (int i = 0; i < 4; i++) oacc[nt][i] = 0.0f;

    for (int t = 0; t <= qtile; t++) {
        const int buf = t & 1;

        CP_WAIT0();
        __syncthreads();

        if (t < qtile) issue_tile(t + 1, buf ^ 1);

        const uint2* KT = (const uint2*)sm + (size_t)buf * BUF_U2;
        const uint2* VT = KT + KTILE_U2;

        // ---- S = Q K^T ----
        float sacc[8][4];
#pragma unroll
        for (int nt = 0; nt < 8; nt++)
#pragma unroll
            for (int i = 0; i < 4; i++) sacc[nt][i] = 0.0f;

#pragma unroll
        for (int kk = 0; kk < 4; kk++) {
            uint2 bq[8];
#pragma unroll
            for (int nt = 0; nt < 8; nt++)
                bq[nt] = KT[(4*kk + qd)*KVS_U2 + nt*8 + g];
#pragma unroll
            for (int nt = 0; nt < 8; nt++)
                mma_f16(sacc[nt], aQ[kk][0], aQ[kk][1], aQ[kk][2], aQ[kk][3],
                        bq[nt].x, bq[nt].y);
        }

        // ---- causal mask (diagonal tile only) ----
        if (t == qtile) {
            const int ra = r0 + g, rb = ra + 8;
#pragma unroll
            for (int nt = 0; nt < 8; nt++) {
                const int ca = nt*8 + qd*2;
                if (ca     > ra) sacc[nt][0] = -1e30f;
                if (ca + 1 > ra) sacc[nt][1] = -1e30f;
                if (ca     > rb) sacc[nt][2] = -1e30f;
                if (ca + 1 > rb) sacc[nt][3] = -1e30f;
            }
        }

        // ---- online softmax; P packed to half2 in registers ----
        uint32_t pA[8], pB[8];
#pragma unroll
        for (int rr = 0; rr < 2; rr++) {
            float lm = -1e30f;
#pragma unroll
            for (int nt = 0; nt < 8; nt++)
                lm = fmaxf(lm, fmaxf(sacc[nt][2*rr], sacc[nt][2*rr+1]));
            lm = fmaxf(lm, __shfl_xor_sync(FULL, lm, 1));
            lm = fmaxf(lm, __shfl_xor_sync(FULL, lm, 2));
            float mnew  = fmaxf(m_[rr], lm);
            float alpha = __expf(m_[rr] - mnew);

            float ls = 0.0f;
#pragma unroll
            for (int nt = 0; nt < 8; nt++) {
                float p0 = __expf(sacc[nt][2*rr]   - mnew);
                float p1 = __expf(sacc[nt][2*rr+1] - mnew);
                ls += p0 + p1;
                uint32_t pk = h2u(__floats2half2_rn(p0, p1));
                if (rr == 0) pA[nt] = pk; else pB[nt] = pk;
            }
            ls += __shfl_xor_sync(FULL, ls, 1);
            ls += __shfl_xor_sync(FULL, ls, 2);

            m_[rr] = mnew;
            l_[rr] = l_[rr]*alpha + ls;
#pragma unroll
            for (int nt = 0; nt < 8; nt++) {
                oacc[nt][2*rr]   *= alpha;
                oacc[nt][2*rr+1] *= alpha;
            }
        }

        // ---- O += P V ----
#pragma unroll
        for (int kk = 0; kk < 4; kk++) {
            uint2 bv[8];
#pragma unroll
            for (int nt = 0; nt < 8; nt++)
                bv[nt] = VT[(4*kk + qd)*KVS_U2 + nt*8 + g];
#pragma unroll
            for (int nt = 0; nt < 8; nt++)
                mma_f16(oacc[nt], pA[2*kk], pB[2*kk], pA[2*kk+1], pB[2*kk+1],
                        bv[nt].x, bv[nt].y);
        }
    }

    // ---- normalize + store as half, A-permuted k-groups ----
    // half2 j = 4nt+qd within group nt>>1 -> pos = 2qd + (nt&1)
#pragma unroll
    for (int rr = 0; rr < 2; rr++) {
        const float inv = 1.0f / l_[rr];
        __half2* op = (__half2*)(go + ((size_t)(b*TDIM + qbase + r0 + g + rr*8))*CDIM + h*HD);
#pragma unroll
        for (int nt = 0; nt < 8; nt++) {
            op[(nt>>1)*8 + 2*qd + (nt&1)] =
                __floats2half2_rn(oacc[nt][2*rr]*inv, oacc[nt][2*rr+1]*inv);
        }
    }
}

// =========================================================================
// launch
// =========================================================================
extern "C" void kernel_launch(void* const* d_in, const int* in_sizes, int n_in,
                              void* d_out, int out_size)
{
    const float* x  = (const float*)d_in[0];
    const float* Wq = (const float*)d_in[1];
    const float* bq = (const float*)d_in[2];
    const float* Wk = (const float*)d_in[3];
    const float* bk = (const float*)d_in[4];
    const float* Wv = (const float*)d_in[5];
    const float* bv = (const float*)d_in[6];
    const float* Wo = (const float*)d_in[7];
    const float* bo = (const float*)d_in[8];
    float* out = (float*)d_out;

    float *qp, *kp;
    __half *k2p, *vp, *ap, *xh;
    uint2 *wqp, *wop, *wkvp;
    cudaGetSymbolAddress((void**)&qp,   g_q);
    cudaGetSymbolAddress((void**)&kp,   g_k);
    cudaGetSymbolAddress((void**)&k2p,  g_k2h);
    cudaGetSymbolAddress((void**)&vp,   g_vh);
    cudaGetSymbolAddress((void**)&ap,   g_atth);
    cudaGetSymbolAddress((void**)&xh,   g_xh);
    cudaGetSymbolAddress((void**)&wqp,  g_wqp);
    cudaGetSymbolAddress((void**)&wop,  g_wop);
    cudaGetSymbolAddress((void**)&wkvp, g_wkvp);

    cudaFuncSetAttribute(hgemm_kernel,
        cudaFuncAttributeMaxDynamicSharedMemorySize, GH_SMEM);
    cudaFuncSetAttribute(attn_tc_kernel,
        cudaFuncAttributeMaxDynamicSharedMemorySize, ATT_SMEM_BYTES);

    // prep: x -> permuted half; Wq/Wo/[Wk|Wv] -> quad-pair u2
    {
        int ng = MROWS*CDIM/16;
        f2h_perm_kernel<<<(ng + 255)/256, 256>>>((const float4*)x, (uint4*)xh, ng);
        pairB2_kernel<<<(256*256 + 255)/256, 256>>>(Wq, (uint4*)wqp);
        pairB2_kernel<<<(256*256 + 255)/256, 256>>>(Wo, (uint4*)wop);
        pairKV2_kernel<<<(256*32 + 255)/256, 256>>>(Wk, Wv, (uint4*)wkvp);
    }

    // Q = x@Wq+bq  AND  K/V = x@[Wk|Wv]+b  in ONE fp16 launch (tile x==8 -> KV)
    hgemm_kernel<<<dim3(9, MROWS/128), 256, GH_SMEM>>>(
        xh, wqp, bq, qp,  wkvp, bk, bv, kp, vp);

    // RoPE: q in-place, k natural -> quad-pair half tiles
    {
        int total = BDIM*TDIM*(NH+1)*(HD/2);
        rope_kernel<<<(total + 255)/256, 256>>>(qp, kp, k2p);
    }

    // causal MQA attention (fp16, LDS.64 loads) -> permuted half att
    attn_tc_kernel<<<dim3(TDIM/64, NH, BDIM), 128, ATT_SMEM_BYTES>>>(
        qp, k2p, vp, ap);

    // out = att @ Wo + bo  (fp16 GEMM; att already permuted half)
    hgemm_kernel<<<dim3(8, MROWS/128), 256, GH_SMEM>>>(
        ap, wop, bo, out,  wkvp, bk, bv, kp, vp);   // KV path unused (grid.x=8)
}